// round 4
// baseline (speedup 1.0000x reference)
#include <cuda_runtime.h>
#include <math.h>

// ---------------- problem constants ----------------
#define TOKENS   4096      // B * Q_LEN
#define HIDDEN_D 4096
#define NHEAD    32
#define HD       128
#define QLEN     512
#define BATCH    8
#define BS64     64        // paged-cache block size == our KV tile
#define NBLK     16

// ---------------- scratch (device globals: no runtime alloc allowed) ----------------
__device__ float g_q[(size_t)TOKENS * HIDDEN_D];
__device__ float g_k[(size_t)TOKENS * HIDDEN_D];
__device__ float g_v[(size_t)TOKENS * HIDDEN_D];
__device__ float g_o[(size_t)TOKENS * HIDDEN_D];

// =====================================================================
// GEMM: C[M,N] = A[M,K] @ B[K,N], row-major fp32, M=N=K multiples of 128/16.
// 128x128 block tile, BK=16, 256 threads, 8x8 per-thread, reg-prefetch
// double buffering over a single smem buffer.
// =====================================================================
__global__ __launch_bounds__(256, 2)
void sgemm_k(const float* __restrict__ A, const float* __restrict__ B,
             float* __restrict__ C, int K, int N)
{
    __shared__ float4 AsV[16][32];   // As[k][m] transposed (viewed as floats)
    __shared__ float4 BsV[16][32];   // Bs[k][n]
    float* As = (float*)AsV;

    const int tid = threadIdx.x;
    const int tx = tid & 15, ty = tid >> 4;
    const int brow = blockIdx.y * 128;
    const int bcol = blockIdx.x * 128;
    const int K4 = K >> 2, N4 = N >> 2;
    const float4* A4 = (const float4*)A;
    const float4* B4 = (const float4*)B;

    // load-index precompute: A tile 128x16 = 512 float4, B tile 16x128 = 512 float4
    const int i0 = tid, i1 = tid + 256;
    const int ar0 = i0 >> 2, ac0 = i0 & 3;
    const int ar1 = i1 >> 2, ac1 = i1 & 3;
    const int br0 = i0 >> 5, bc0 = i0 & 31;
    const int br1 = i1 >> 5, bc1 = i1 & 31;

    float acc[8][8];
#pragma unroll
    for (int i = 0; i < 8; i++)
#pragma unroll
        for (int j = 0; j < 8; j++) acc[i][j] = 0.f;

    // ---- initial tile -> smem ----
    {
        float4 a0 = A4[(size_t)(brow + ar0) * K4 + ac0];
        float4 a1 = A4[(size_t)(brow + ar1) * K4 + ac1];
        float4 b0 = B4[(size_t)br0 * N4 + (bcol >> 2) + bc0];
        float4 b1 = B4[(size_t)br1 * N4 + (bcol >> 2) + bc1];
        As[(ac0*4+0)*128 + ar0] = a0.x; As[(ac0*4+1)*128 + ar0] = a0.y;
        As[(ac0*4+2)*128 + ar0] = a0.z; As[(ac0*4+3)*128 + ar0] = a0.w;
        As[(ac1*4+0)*128 + ar1] = a1.x; As[(ac1*4+1)*128 + ar1] = a1.y;
        As[(ac1*4+2)*128 + ar1] = a1.z; As[(ac1*4+3)*128 + ar1] = a1.w;
        BsV[br0][bc0] = b0; BsV[br1][bc1] = b1;
    }
    __syncthreads();

    const int nT = K >> 4;
    for (int t = 0; t < nT; t++) {
        float4 pa0, pa1, pb0, pb1;
        const bool has = (t + 1 < nT);
        if (has) {
            const int kof = (t + 1) << 2;   // float4 offset along K
            const int kr  = (t + 1) << 4;   // row offset in B
            pa0 = A4[(size_t)(brow + ar0) * K4 + kof + ac0];
            pa1 = A4[(size_t)(brow + ar1) * K4 + kof + ac1];
            pb0 = B4[(size_t)(kr + br0) * N4 + (bcol >> 2) + bc0];
            pb1 = B4[(size_t)(kr + br1) * N4 + (bcol >> 2) + bc1];
        }
#pragma unroll
        for (int kk = 0; kk < 16; kk++) {
            float4 a0 = AsV[kk][ty*2], a1 = AsV[kk][ty*2 + 1];
            float4 b0 = BsV[kk][tx*2], b1 = BsV[kk][tx*2 + 1];
            float av[8] = {a0.x,a0.y,a0.z,a0.w,a1.x,a1.y,a1.z,a1.w};
            float bv[8] = {b0.x,b0.y,b0.z,b0.w,b1.x,b1.y,b1.z,b1.w};
#pragma unroll
            for (int i = 0; i < 8; i++)
#pragma unroll
                for (int j = 0; j < 8; j++) acc[i][j] += av[i] * bv[j];
        }
        __syncthreads();
        if (has) {
            As[(ac0*4+0)*128 + ar0] = pa0.x; As[(ac0*4+1)*128 + ar0] = pa0.y;
            As[(ac0*4+2)*128 + ar0] = pa0.z; As[(ac0*4+3)*128 + ar0] = pa0.w;
            As[(ac1*4+0)*128 + ar1] = pa1.x; As[(ac1*4+1)*128 + ar1] = pa1.y;
            As[(ac1*4+2)*128 + ar1] = pa1.z; As[(ac1*4+3)*128 + ar1] = pa1.w;
            BsV[br0][bc0] = pb0; BsV[br1][bc1] = pb1;
            __syncthreads();
        }
    }

    float4* C4 = (float4*)C;
#pragma unroll
    for (int i = 0; i < 8; i++) {
        size_t row = (size_t)brow + ty*8 + i;
        C4[row * N4 + (bcol >> 2) + tx*2]     = make_float4(acc[i][0], acc[i][1], acc[i][2], acc[i][3]);
        C4[row * N4 + (bcol >> 2) + tx*2 + 1] = make_float4(acc[i][4], acc[i][5], acc[i][6], acc[i][7]);
    }
}

// =====================================================================
// RoPE (in-place on g_q, g_k). One thread per (token, head, d<64).
// inv_freq[d] = 10000^(-d/64) computed as exp2f(-d * log2(10000)/64).
// =====================================================================
__global__ void rope_k(const int* __restrict__ pos)
{
    int idx = blockIdx.x * blockDim.x + threadIdx.x;
    if (idx >= TOKENS * NHEAD * 64) return;
    int d   = idx & 63;
    int th  = idx >> 6;        // token*NHEAD + head
    int tok = th >> 5;
    float p = (float)pos[tok];
    float f = p * exp2f(-0.207620505930454f * (float)d);  // log2(10000)/64
    float s, c;
    sincosf(f, &s, &c);
    size_t base = (size_t)th * HD;
    float x1 = g_q[base + d], x2 = g_q[base + d + 64];
    g_q[base + d]      = x1 * c - x2 * s;
    g_q[base + d + 64] = x2 * c + x1 * s;
    x1 = g_k[base + d]; x2 = g_k[base + d + 64];
    g_k[base + d]      = x1 * c - x2 * s;
    g_k[base + d + 64] = x2 * c + x1 * s;
}

// =====================================================================
// Flash attention over paged KV.
// Grid: (QLEN/64, NHEAD, BATCH). Block: 256 threads (16x16).
// Q tile 64x128, KV tiles of 64 rows (== one cache block).
// Tiles t<8 come from the paged cache (history), t>=8 from g_k/g_v
// (fresh RoPE'd K/V — same row stride NHEAD*HD in both layouts).
// =====================================================================
#define QS_STRIDE 129
#define SS_STRIDE 65
#define VS_STRIDE4 33   // 132 floats

#define SM_QS   0
#define SM_KS   (64*129)                 // 8256
#define SM_VS   (SM_KS + 64*129)         // 16512
#define SM_SS   (SM_VS + 64*132)         // 24960
#define SM_PMAX (SM_SS + 64*65)          // 29120
#define SM_PSUM (SM_PMAX + 64*16)        // 30144
#define SM_M    (SM_PSUM + 64*16)        // 31168
#define SM_L    (SM_M + 64)
#define SM_SC   (SM_L + 64)
#define SMEM_FLOATS (SM_SC + 64)         // 31360 floats
#define SMEM_BYTES  (SMEM_FLOATS * 4)    // 125440 B

__global__ __launch_bounds__(256, 1)
void attn_k(const float* __restrict__ kcache, const float* __restrict__ vcache,
            const int* __restrict__ btab, const int* __restrict__ pos,
            const int* __restrict__ kvlen_arr)
{
    extern __shared__ float sm[];
    float* Qs   = sm + SM_QS;
    float* Ks   = sm + SM_KS;
    float* Vs   = sm + SM_VS;
    float* Ss   = sm + SM_SS;
    float* pmax = sm + SM_PMAX;
    float* psum = sm + SM_PSUM;
    float* mrow = sm + SM_M;
    float* lrow = sm + SM_L;
    float* srow = sm + SM_SC;

    const int qt = blockIdx.x, h = blockIdx.y, b = blockIdx.z;
    const int tid = threadIdx.x;
    const int tx = tid & 15, ty = tid >> 4;
    const int kvlen = kvlen_arr[b];
    const int tok0  = b * QLEN + qt * 64;
    const int qpos0 = pos[tok0];   // row r has position qpos0 + r

    // ---- load Q tile ----
    const float4* gq4 = (const float4*)g_q;
    for (int i = tid; i < 2048; i += 256) {
        int r = i >> 5, c4 = i & 31;
        float4 qv = gq4[((size_t)(tok0 + r) * NHEAD + h) * (HD/4) + c4];
        float* dst = Qs + r * QS_STRIDE + c4 * 4;
        dst[0] = qv.x; dst[1] = qv.y; dst[2] = qv.z; dst[3] = qv.w;
    }
    if (tid < 64) { mrow[tid] = -3.0e38f; lrow[tid] = 0.f; }

    float o_acc[4][8];
#pragma unroll
    for (int i = 0; i < 4; i++)
#pragma unroll
        for (int c = 0; c < 8; c++) o_acc[i][c] = 0.f;

    int tmax = (qpos0 + 63) >> 6;            // last tile touched by causal mask
    int tkv  = (kvlen - 1) >> 6;
    if (tmax > tkv) tmax = tkv;
    if (tmax > NBLK - 1) tmax = NBLK - 1;

    const float scl = 0.0883883476483184f;   // 1/sqrt(128)

    for (int t = 0; t <= tmax; t++) {
        const float* ksrc; const float* vsrc;
        if (t < 8) {  // history: paged cache, [slot][head][hd], row stride NHEAD*HD
            int pb = btab[b * NBLK + t];
            size_t base = ((size_t)pb * BS64 * NHEAD + h) * HD;
            ksrc = kcache + base; vsrc = vcache + base;
        } else {      // fresh tokens: g_k/g_v [tok][head][hd], same row stride
            int tokk = b * QLEN + (t - 8) * 64;
            size_t base = ((size_t)tokk * NHEAD + h) * HD;
            ksrc = g_k + base; vsrc = g_v + base;
        }
        __syncthreads();  // end-of-previous-tile / Q-load barrier

        for (int i = tid; i < 2048; i += 256) {
            int r = i >> 5, c4 = i & 31;
            float4 kv4 = *(const float4*)(ksrc + (size_t)r * (NHEAD*HD) + c4*4);
            float* kd = Ks + r * QS_STRIDE + c4 * 4;
            kd[0] = kv4.x; kd[1] = kv4.y; kd[2] = kv4.z; kd[3] = kv4.w;
            float4 vv4 = *(const float4*)(vsrc + (size_t)r * (NHEAD*HD) + c4*4);
            ((float4*)Vs)[r * VS_STRIDE4 + c4] = vv4;
        }
        __syncthreads();

        // ---- S = Q K^T (4x4 per thread) ----
        float sacc[4][4];
#pragma unroll
        for (int i = 0; i < 4; i++)
#pragma unroll
            for (int j = 0; j < 4; j++) sacc[i][j] = 0.f;
        const float* qb = Qs + (ty * 4) * QS_STRIDE;
        const float* kb = Ks + (tx * 4) * QS_STRIDE;
#pragma unroll 8
        for (int k = 0; k < HD; k++) {
            float aa[4], bb[4];
#pragma unroll
            for (int i = 0; i < 4; i++) aa[i] = qb[i * QS_STRIDE + k];
#pragma unroll
            for (int j = 0; j < 4; j++) bb[j] = kb[j * QS_STRIDE + k];
#pragma unroll
            for (int i = 0; i < 4; i++)
#pragma unroll
                for (int j = 0; j < 4; j++) sacc[i][j] += aa[i] * bb[j];
        }

        // ---- scale + causal mask + store + per-thread row max ----
        const int kvbase = t * 64 + tx * 4;
#pragma unroll
        for (int i = 0; i < 4; i++) {
            int qp = qpos0 + ty * 4 + i;
            float pm = -3.0e38f;
#pragma unroll
            for (int j = 0; j < 4; j++) {
                float sv = sacc[i][j] * scl;
                int kvp = kvbase + j;
                if (kvp > qp || kvp >= kvlen) sv = -3.0e38f;
                Ss[(ty*4 + i) * SS_STRIDE + tx*4 + j] = sv;
                pm = fmaxf(pm, sv);
            }
            pmax[(ty*4 + i) * 16 + tx] = pm;
        }
        __syncthreads();

        // ---- online-softmax row state (64 threads) ----
        if (tid < 64) {
            float m0 = mrow[tid];
            float tm = -3.0e38f;
#pragma unroll
            for (int u = 0; u < 16; u++) tm = fmaxf(tm, pmax[tid*16 + u]);
            float mn = fmaxf(m0, tm);
            float sc = __expf(m0 - mn);
            srow[tid] = sc;
            mrow[tid] = mn;
            lrow[tid] *= sc;
        }
        __syncthreads();

        // ---- exp pass + partial sums + rescale O ----
#pragma unroll
        for (int i = 0; i < 4; i++) {
            int r = ty*4 + i;
            float mr = mrow[r];
            float s = 0.f;
#pragma unroll
            for (int j = 0; j < 4; j++) {
                float pv = __expf(Ss[r * SS_STRIDE + tx*4 + j] - mr);
                Ss[r * SS_STRIDE + tx*4 + j] = pv;
                s += pv;
            }
            psum[r * 16 + tx] = s;
            float sc = srow[r];
#pragma unroll
            for (int c = 0; c < 8; c++) o_acc[i][c] *= sc;
        }
        __syncthreads();

        if (tid < 64) {
            float s = 0.f;
#pragma unroll
            for (int u = 0; u < 16; u++) s += psum[tid*16 + u];
            lrow[tid] += s;
        }

        // ---- O += P @ V ----
        const float4* vsv = (const float4*)Vs;
#pragma unroll 4
        for (int j = 0; j < 64; j++) {
            float4 v0 = vsv[j * VS_STRIDE4 + tx*2];
            float4 v1 = vsv[j * VS_STRIDE4 + tx*2 + 1];
            float p0 = Ss[(ty*4 + 0) * SS_STRIDE + j];
            float p1 = Ss[(ty*4 + 1) * SS_STRIDE + j];
            float p2 = Ss[(ty*4 + 2) * SS_STRIDE + j];
            float p3 = Ss[(ty*4 + 3) * SS_STRIDE + j];
            o_acc[0][0] += p0*v0.x; o_acc[0][1] += p0*v0.y; o_acc[0][2] += p0*v0.z; o_acc[0][3] += p0*v0.w;
            o_acc[0][4] += p0*v1.x; o_acc[0][5] += p0*v1.y; o_acc[0][6] += p0*v1.z; o_acc[0][7] += p0*v1.w;
            o_acc[1][0] += p1*v0.x; o_acc[1][1] += p1*v0.y; o_acc[1][2] += p1*v0.z; o_acc[1][3] += p1*v0.w;
            o_acc[1][4] += p1*v1.x; o_acc[1][5] += p1*v1.y; o_acc[1][6] += p1*v1.z; o_acc[1][7] += p1*v1.w;
            o_acc[2][0] += p2*v0.x; o_acc[2][1] += p2*v0.y; o_acc[2][2] += p2*v0.z; o_acc[2][3] += p2*v0.w;
            o_acc[2][4] += p2*v1.x; o_acc[2][5] += p2*v1.y; o_acc[2][6] += p2*v1.z; o_acc[2][7] += p2*v1.w;
            o_acc[3][0] += p3*v0.x; o_acc[3][1] += p3*v0.y; o_acc[3][2] += p3*v0.z; o_acc[3][3] += p3*v0.w;
            o_acc[3][4] += p3*v1.x; o_acc[3][5] += p3*v1.y; o_acc[3][6] += p3*v1.z; o_acc[3][7] += p3*v1.w;
        }
    }
    __syncthreads();

    // ---- normalize + write to g_o [tok][head][hd] ----
    float4* go4 = (float4*)g_o;
#pragma unroll
    for (int i = 0; i < 4; i++) {
        int r = ty*4 + i;
        float inv = 1.f / lrow[r];
        size_t tok = (size_t)tok0 + r;
        float4 w0 = make_float4(o_acc[i][0]*inv, o_acc[i][1]*inv, o_acc[i][2]*inv, o_acc[i][3]*inv);
        float4 w1 = make_float4(o_acc[i][4]*inv, o_acc[i][5]*inv, o_acc[i][6]*inv, o_acc[i][7]*inv);
        go4[tok * (HIDDEN_D/4) + h * (HD/4) + tx*2]     = w0;
        go4[tok * (HIDDEN_D/4) + h * (HD/4) + tx*2 + 1] = w1;
    }
}

// =====================================================================
// Launch: QKV GEMMs -> RoPE -> flash attention -> output GEMM.
// (The paged cache is never mutated: fresh K/V live in g_k/g_v and are
//  read directly by attention for kv tiles >= HIST/BS.)
// =====================================================================
extern "C" void kernel_launch(void* const* d_in, const int* in_sizes, int n_in,
                              void* d_out, int out_size)
{
    const float* hidden = (const float*)d_in[0];
    const float* Wq     = (const float*)d_in[1];
    const float* Wk     = (const float*)d_in[2];
    const float* Wv     = (const float*)d_in[3];
    const float* Wo     = (const float*)d_in[4];
    const float* kc     = (const float*)d_in[5];
    const float* vc     = (const float*)d_in[6];
    const int*   btab   = (const int*)d_in[7];
    const int*   pos    = (const int*)d_in[8];
    const int*   kvl    = (const int*)d_in[9];
    float* out = (float*)d_out;

    float *pq = nullptr, *pk = nullptr, *pv = nullptr, *po = nullptr;
    cudaGetSymbolAddress((void**)&pq, g_q);
    cudaGetSymbolAddress((void**)&pk, g_k);
    cudaGetSymbolAddress((void**)&pv, g_v);
    cudaGetSymbolAddress((void**)&po, g_o);

    dim3 gg(HIDDEN_D / 128, TOKENS / 128);
    dim3 bb(256);
    sgemm_k<<<gg, bb>>>(hidden, Wq, pq, HIDDEN_D, HIDDEN_D);
    sgemm_k<<<gg, bb>>>(hidden, Wk, pk, HIDDEN_D, HIDDEN_D);
    sgemm_k<<<gg, bb>>>(hidden, Wv, pv, HIDDEN_D, HIDDEN_D);

    rope_k<<<(TOKENS * NHEAD * 64) / 256, 256>>>(pos);

    cudaFuncSetAttribute(attn_k, cudaFuncAttributeMaxDynamicSharedMemorySize, SMEM_BYTES);
    attn_k<<<dim3(QLEN / 64, NHEAD, BATCH), 256, SMEM_BYTES>>>(kc, vc, btab, pos, kvl);

    sgemm_k<<<gg, bb>>>(po, Wo, out, HIDDEN_D, HIDDEN_D);
}

// round 7
// speedup vs baseline: 1.7205x; 1.7205x over previous
#include <cuda_runtime.h>
#include <cuda_bf16.h>
#include <cstdint>
#include <math.h>

// ---------------- problem constants ----------------
#define TOKENS   4096      // B * Q_LEN
#define HIDDEN_D 4096
#define NHEAD    32
#define HD       128
#define QLEN     512
#define BATCH    8
#define BS64     64
#define NBLK     16

#define KSPLIT   12288     // 3 * 4096 (hi*hi | hi*lo | lo*hi)

// ---------------- scratch (device globals: no runtime alloc allowed) ----------------
__device__ float g_q[(size_t)TOKENS * HIDDEN_D];
__device__ float g_k[(size_t)TOKENS * HIDDEN_D];
__device__ float g_v[(size_t)TOKENS * HIDDEN_D];
__device__ float g_o[(size_t)TOKENS * HIDDEN_D];
__device__ __nv_bfloat16 g_as[(size_t)TOKENS * KSPLIT];    // A' = [hi | hi | lo]
__device__ __nv_bfloat16 g_bs[(size_t)HIDDEN_D * KSPLIT];  // B' = [Wt_hi | Wt_lo | Wt_hi]

// =====================================================================
// PTX helpers (baseline ISA only: ldmatrix / mma.sync / cp.async)
// =====================================================================
__device__ __forceinline__ uint32_t smem_u32(const void* p) {
    uint32_t a;
    asm("{ .reg .u64 t; cvta.to.shared.u64 t, %1; cvt.u32.u64 %0, t; }" : "=r"(a) : "l"(p));
    return a;
}
__device__ __forceinline__ void cpasync16(uint32_t s, const void* g) {
    asm volatile("cp.async.cg.shared.global [%0], [%1], 16;" :: "r"(s), "l"(g));
}
#define CP_COMMIT() asm volatile("cp.async.commit_group;" ::: "memory")
#define CP_WAIT(n)  asm volatile("cp.async.wait_group %0;" :: "n"(n) : "memory")

__device__ __forceinline__ void ldsm_x4(uint32_t* r, uint32_t addr) {
    asm volatile("ldmatrix.sync.aligned.m8n8.x4.shared.b16 {%0,%1,%2,%3}, [%4];"
        : "=r"(r[0]), "=r"(r[1]), "=r"(r[2]), "=r"(r[3]) : "r"(addr));
}
__device__ __forceinline__ void ldsm_x2(uint32_t* r, uint32_t addr) {
    asm volatile("ldmatrix.sync.aligned.m8n8.x2.shared.b16 {%0,%1}, [%2];"
        : "=r"(r[0]), "=r"(r[1]) : "r"(addr));
}
__device__ __forceinline__ void mma16816(float* c, const uint32_t* a, const uint32_t* b) {
    asm volatile("mma.sync.aligned.m16n8k16.row.col.f32.bf16.bf16.f32 "
        "{%0,%1,%2,%3}, {%4,%5,%6,%7}, {%8,%9}, {%0,%1,%2,%3};"
        : "+f"(c[0]), "+f"(c[1]), "+f"(c[2]), "+f"(c[3])
        : "r"(a[0]), "r"(a[1]), "r"(a[2]), "r"(a[3]), "r"(b[0]), "r"(b[1]));
}

// =====================================================================
// Split kernels: fp32 -> (hi, lo) bf16, arranged for K' = 3*4096 GEMM.
// A' row m: [hi(X[m,:]) | hi(X[m,:]) | lo(X[m,:])]
// B' row n: [hi(W[:,n]) | lo(W[:,n]) | hi(W[:,n])]   (transposed weights)
// =====================================================================
__global__ void split_a_k(const float* __restrict__ X, __nv_bfloat16* __restrict__ As)
{
    int idx = blockIdx.x * blockDim.x + threadIdx.x;   // < 4096*1024
    int m = idx >> 10, k4 = idx & 1023;
    float4 x = ((const float4*)X)[(size_t)m * 1024 + k4];
    float xs[4] = {x.x, x.y, x.z, x.w};
    union { __nv_bfloat16 b[4]; uint2 u; } H, L;
#pragma unroll
    for (int i = 0; i < 4; i++) {
        H.b[i] = __float2bfloat16(xs[i]);
        L.b[i] = __float2bfloat16(xs[i] - __bfloat162float(H.b[i]));
    }
    size_t base = (size_t)m * KSPLIT + k4 * 4;
    *(uint2*)(As + base)        = H.u;
    *(uint2*)(As + base + 4096) = H.u;
    *(uint2*)(As + base + 8192) = L.u;
}

__global__ void split_wt_k(const float* __restrict__ W, __nv_bfloat16* __restrict__ Bs)
{
    __shared__ float t[32][33];
    int n0 = blockIdx.x * 32, k0 = blockIdx.y * 32;
    int tx = threadIdx.x, ty = threadIdx.y;   // (32, 8)
#pragma unroll
    for (int i = 0; i < 4; i++)
        t[ty + i * 8][tx] = W[(size_t)(k0 + ty + i * 8) * HIDDEN_D + n0 + tx];
    __syncthreads();
#pragma unroll
    for (int i = 0; i < 4; i++) {
        int n = n0 + ty + i * 8, kk = k0 + tx;
        float x = t[tx][ty + i * 8];
        __nv_bfloat16 h = __float2bfloat16(x);
        __nv_bfloat16 l = __float2bfloat16(x - __bfloat162float(h));
        size_t base = (size_t)n * KSPLIT + kk;
        Bs[base]        = h;
        Bs[base + 4096] = l;
        Bs[base + 8192] = h;
    }
}

// =====================================================================
// HMMA GEMM: C[4096,4096] fp32 = A'[4096,K'] x B'[4096,K']^T
// CTA tile 128x256x32, 512 threads (16 warps, warp tile 64x32),
// 3-stage cp.async pipeline, smem row stride 80B (conflict-free ldmatrix).
// =====================================================================
#define BM 128
#define BN 256
#define BK 32
#define ROWB 80                       // smem bytes per row (32 bf16 + 16B pad)
#define A_STAGE (BM * ROWB)           // 10240
#define B_STAGE (BN * ROWB)           // 20480
#define STAGE_B (A_STAGE + B_STAGE)   // 30720
#define NSTAGE 3
#define MG_SMEM (STAGE_B * NSTAGE)    // 92160
#define NT_CHUNKS (KSPLIT / BK)       // 384

__global__ __launch_bounds__(512, 1)
void mma_gemm_k(const __nv_bfloat16* __restrict__ A, const __nv_bfloat16* __restrict__ Bt,
                float* __restrict__ C)
{
    extern __shared__ char smem[];
    const uint32_t sbase = smem_u32(smem);
    const int tid  = threadIdx.x;
    const int lane = tid & 31, wid = tid >> 5;
    const int warp_m = wid >> 3;          // 0..1
    const int warp_n = wid & 7;           // 0..7
    const int brow = blockIdx.y * BM;
    const int bcol = blockIdx.x * BN;

    // per-stage load: A 512 chunks (tid), B 1024 chunks (tid, tid+512)
    const int ar = tid >> 2, ac = tid & 3;
    const int br0 = tid >> 2, bc0 = tid & 3;
    const int br1 = (tid + 512) >> 2, bc1 = tid & 3;

    float acc[4][4][4];
#pragma unroll
    for (int i = 0; i < 4; i++)
#pragma unroll
        for (int j = 0; j < 4; j++)
#pragma unroll
            for (int q = 0; q < 4; q++) acc[i][j][q] = 0.f;

#define LOAD_STAGE(st, kc) do {                                                       \
    uint32_t sA = sbase + (st) * STAGE_B;                                             \
    uint32_t sB = sA + A_STAGE;                                                       \
    cpasync16(sA + ar * ROWB + ac * 16, A  + (size_t)(brow + ar)  * KSPLIT + (kc) + ac  * 8);  \
    cpasync16(sB + br0 * ROWB + bc0 * 16, Bt + (size_t)(bcol + br0) * KSPLIT + (kc) + bc0 * 8); \
    cpasync16(sB + br1 * ROWB + bc1 * 16, Bt + (size_t)(bcol + br1) * KSPLIT + (kc) + bc1 * 8); \
} while (0)

    LOAD_STAGE(0, 0);  CP_COMMIT();
    LOAD_STAGE(1, BK); CP_COMMIT();

    // precomputed ldmatrix lane address components
    const uint32_t a_row  = (uint32_t)(warp_m * 64 + (lane & 15));
    const uint32_t a_kh   = (uint32_t)((lane >> 4) << 3);
    const uint32_t b_row  = (uint32_t)(warp_n * 32 + (lane & 7));
    const uint32_t b_kh   = (uint32_t)(((lane >> 3) & 1) << 3);

    for (int t = 0; t < NT_CHUNKS; t++) {
        CP_WAIT(1);
        __syncthreads();
        if (t + 2 < NT_CHUNKS) LOAD_STAGE((t + 2) % NSTAGE, (t + 2) * BK);
        CP_COMMIT();

        const uint32_t sA = sbase + (t % NSTAGE) * STAGE_B;
        const uint32_t sB = sA + A_STAGE;

#pragma unroll
        for (int ks = 0; ks < 2; ks++) {
            uint32_t af[4][4], bfr[4][2];
            const uint32_t ka = (uint32_t)(ks * 16) + a_kh;
            const uint32_t kb = (uint32_t)(ks * 16) + b_kh;
#pragma unroll
            for (int i = 0; i < 4; i++)
                ldsm_x4(af[i], sA + (a_row + i * 16) * ROWB + ka * 2);
#pragma unroll
            for (int j = 0; j < 4; j++)
                ldsm_x2(bfr[j], sB + (b_row + j * 8) * ROWB + kb * 2);
#pragma unroll
            for (int i = 0; i < 4; i++)
#pragma unroll
                for (int j = 0; j < 4; j++)
                    mma16816(acc[i][j], af[i], bfr[j]);
        }
    }
#undef LOAD_STAGE

    // epilogue
#pragma unroll
    for (int i = 0; i < 4; i++) {
        int row0 = brow + warp_m * 64 + i * 16 + (lane >> 2);
#pragma unroll
        for (int j = 0; j < 4; j++) {
            int col = bcol + warp_n * 32 + j * 8 + (lane & 3) * 2;
            *(float2*)(C + (size_t)row0 * HIDDEN_D + col)       = make_float2(acc[i][j][0], acc[i][j][1]);
            *(float2*)(C + (size_t)(row0 + 8) * HIDDEN_D + col) = make_float2(acc[i][j][2], acc[i][j][3]);
        }
    }
}

// =====================================================================
// RoPE (in-place on g_q, g_k).
// =====================================================================
__global__ void rope_k(const int* __restrict__ pos)
{
    int idx = blockIdx.x * blockDim.x + threadIdx.x;
    if (idx >= TOKENS * NHEAD * 64) return;
    int d   = idx & 63;
    int th  = idx >> 6;
    int tok = th >> 5;
    float p = (float)pos[tok];
    float f = p * exp2f(-0.207620505930454f * (float)d);  // log2(10000)/64
    float s, c;
    sincosf(f, &s, &c);
    size_t base = (size_t)th * HD;
    float x1 = g_q[base + d], x2 = g_q[base + d + 64];
    g_q[base + d]      = x1 * c - x2 * s;
    g_q[base + d + 64] = x2 * c + x1 * s;
    x1 = g_k[base + d]; x2 = g_k[base + d + 64];
    g_k[base + d]      = x1 * c - x2 * s;
    g_k[base + d + 64] = x2 * c + x1 * s;
}

// =====================================================================
// Flash attention over paged KV (unchanged from passing R4 kernel).
// =====================================================================
#define QS_STRIDE 129
#define SS_STRIDE 65
#define VS_STRIDE4 33

#define SM_QS   0
#define SM_KS   (64*129)
#define SM_VS   (SM_KS + 64*129)
#define SM_SS   (SM_VS + 64*132)
#define SM_PMAX (SM_SS + 64*65)
#define SM_PSUM (SM_PMAX + 64*16)
#define SM_M    (SM_PSUM + 64*16)
#define SM_L    (SM_M + 64)
#define SM_SC   (SM_L + 64)
#define SMEM_FLOATS (SM_SC + 64)
#define SMEM_BYTES  (SMEM_FLOATS * 4)

__global__ __launch_bounds__(256, 1)
void attn_k(const float* __restrict__ kcache, const float* __restrict__ vcache,
            const int* __restrict__ btab, const int* __restrict__ pos,
            const int* __restrict__ kvlen_arr)
{
    extern __shared__ float sm[];
    float* Qs   = sm + SM_QS;
    float* Ks   = sm + SM_KS;
    float* Vs   = sm + SM_VS;
    float* Ss   = sm + SM_SS;
    float* pmax = sm + SM_PMAX;
    float* psum = sm + SM_PSUM;
    float* mrow = sm + SM_M;
    float* lrow = sm + SM_L;
    float* srow = sm + SM_SC;

    const int qt = blockIdx.x, h = blockIdx.y, b = blockIdx.z;
    const int tid = threadIdx.x;
    const int tx = tid & 15, ty = tid >> 4;
    const int kvlen = kvlen_arr[b];
    const int tok0  = b * QLEN + qt * 64;
    const int qpos0 = pos[tok0];

    const float4* gq4 = (const float4*)g_q;
    for (int i = tid; i < 2048; i += 256) {
        int r = i >> 5, c4 = i & 31;
        float4 qv = gq4[((size_t)(tok0 + r) * NHEAD + h) * (HD/4) + c4];
        float* dst = Qs + r * QS_STRIDE + c4 * 4;
        dst[0] = qv.x; dst[1] = qv.y; dst[2] = qv.z; dst[3] = qv.w;
    }
    if (tid < 64) { mrow[tid] = -3.0e38f; lrow[tid] = 0.f; }

    float o_acc[4][8];
#pragma unroll
    for (int i = 0; i < 4; i++)
#pragma unroll
        for (int c = 0; c < 8; c++) o_acc[i][c] = 0.f;

    int tmax = (qpos0 + 63) >> 6;
    int tkv  = (kvlen - 1) >> 6;
    if (tmax > tkv) tmax = tkv;
    if (tmax > NBLK - 1) tmax = NBLK - 1;

    const float scl = 0.0883883476483184f;

    for (int t = 0; t <= tmax; t++) {
        const float* ksrc; const float* vsrc;
        if (t < 8) {
            int pb = btab[b * NBLK + t];
            size_t base = ((size_t)pb * BS64 * NHEAD + h) * HD;
            ksrc = kcache + base; vsrc = vcache + base;
        } else {
            int tokk = b * QLEN + (t - 8) * 64;
            size_t base = ((size_t)tokk * NHEAD + h) * HD;
            ksrc = g_k + base; vsrc = g_v + base;
        }
        __syncthreads();

        for (int i = tid; i < 2048; i += 256) {
            int r = i >> 5, c4 = i & 31;
            float4 kv4 = *(const float4*)(ksrc + (size_t)r * (NHEAD*HD) + c4*4);
            float* kd = Ks + r * QS_STRIDE + c4 * 4;
            kd[0] = kv4.x; kd[1] = kv4.y; kd[2] = kv4.z; kd[3] = kv4.w;
            float4 vv4 = *(const float4*)(vsrc + (size_t)r * (NHEAD*HD) + c4*4);
            ((float4*)Vs)[r * VS_STRIDE4 + c4] = vv4;
        }
        __syncthreads();

        float sacc[4][4];
#pragma unroll
        for (int i = 0; i < 4; i++)
#pragma unroll
            for (int j = 0; j < 4; j++) sacc[i][j] = 0.f;
        const float* qb = Qs + (ty * 4) * QS_STRIDE;
        const float* kb = Ks + (tx * 4) * QS_STRIDE;
#pragma unroll 8
        for (int k = 0; k < HD; k++) {
            float aa[4], bb[4];
#pragma unroll
            for (int i = 0; i < 4; i++) aa[i] = qb[i * QS_STRIDE + k];
#pragma unroll
            for (int j = 0; j < 4; j++) bb[j] = kb[j * QS_STRIDE + k];
#pragma unroll
            for (int i = 0; i < 4; i++)
#pragma unroll
                for (int j = 0; j < 4; j++) sacc[i][j] += aa[i] * bb[j];
        }

        const int kvbase = t * 64 + tx * 4;
#pragma unroll
        for (int i = 0; i < 4; i++) {
            int qp = qpos0 + ty * 4 + i;
            float pm = -3.0e38f;
#pragma unroll
            for (int j = 0; j < 4; j++) {
                float sv = sacc[i][j] * scl;
                int kvp = kvbase + j;
                if (kvp > qp || kvp >= kvlen) sv = -3.0e38f;
                Ss[(ty*4 + i) * SS_STRIDE + tx*4 + j] = sv;
                pm = fmaxf(pm, sv);
            }
            pmax[(ty*4 + i) * 16 + tx] = pm;
        }
        __syncthreads();

        if (tid < 64) {
            float m0 = mrow[tid];
            float tm = -3.0e38f;
#pragma unroll
            for (int u = 0; u < 16; u++) tm = fmaxf(tm, pmax[tid*16 + u]);
            float mn = fmaxf(m0, tm);
            float sc = __expf(m0 - mn);
            srow[tid] = sc;
            mrow[tid] = mn;
            lrow[tid] *= sc;
        }
        __syncthreads();

#pragma unroll
        for (int i = 0; i < 4; i++) {
            int r = ty*4 + i;
            float mr = mrow[r];
            float s = 0.f;
#pragma unroll
            for (int j = 0; j < 4; j++) {
                float pv = __expf(Ss[r * SS_STRIDE + tx*4 + j] - mr);
                Ss[r * SS_STRIDE + tx*4 + j] = pv;
                s += pv;
            }
            psum[r * 16 + tx] = s;
            float sc = srow[r];
#pragma unroll
            for (int c = 0; c < 8; c++) o_acc[i][c] *= sc;
        }
        __syncthreads();

        if (tid < 64) {
            float s = 0.f;
#pragma unroll
            for (int u = 0; u < 16; u++) s += psum[tid*16 + u];
            lrow[tid] += s;
        }

        const float4* vsv = (const float4*)Vs;
#pragma unroll 4
        for (int j = 0; j < 64; j++) {
            float4 v0 = vsv[j * VS_STRIDE4 + tx*2];
            float4 v1 = vsv[j * VS_STRIDE4 + tx*2 + 1];
            float p0 = Ss[(ty*4 + 0) * SS_STRIDE + j];
            float p1 = Ss[(ty*4 + 1) * SS_STRIDE + j];
            float p2 = Ss[(ty*4 + 2) * SS_STRIDE + j];
            float p3 = Ss[(ty*4 + 3) * SS_STRIDE + j];
            o_acc[0][0] += p0*v0.x; o_acc[0][1] += p0*v0.y; o_acc[0][2] += p0*v0.z; o_acc[0][3] += p0*v0.w;
            o_acc[0][4] += p0*v1.x; o_acc[0][5] += p0*v1.y; o_acc[0][6] += p0*v1.z; o_acc[0][7] += p0*v1.w;
            o_acc[1][0] += p1*v0.x; o_acc[1][1] += p1*v0.y; o_acc[1][2] += p1*v0.z; o_acc[1][3] += p1*v0.w;
            o_acc[1][4] += p1*v1.x; o_acc[1][5] += p1*v1.y; o_acc[1][6] += p1*v1.z; o_acc[1][7] += p1*v1.w;
            o_acc[2][0] += p2*v0.x; o_acc[2][1] += p2*v0.y; o_acc[2][2] += p2*v0.z; o_acc[2][3] += p2*v0.w;
            o_acc[2][4] += p2*v1.x; o_acc[2][5] += p2*v1.y; o_acc[2][6] += p2*v1.z; o_acc[2][7] += p2*v1.w;
            o_acc[3][0] += p3*v0.x; o_acc[3][1] += p3*v0.y; o_acc[3][2] += p3*v0.z; o_acc[3][3] += p3*v0.w;
            o_acc[3][4] += p3*v1.x; o_acc[3][5] += p3*v1.y; o_acc[3][6] += p3*v1.z; o_acc[3][7] += p3*v1.w;
        }
    }
    __syncthreads();

    float4* go4 = (float4*)g_o;
#pragma unroll
    for (int i = 0; i < 4; i++) {
        int r = ty*4 + i;
        float inv = 1.f / lrow[r];
        size_t tok = (size_t)tok0 + r;
        float4 w0 = make_float4(o_acc[i][0]*inv, o_acc[i][1]*inv, o_acc[i][2]*inv, o_acc[i][3]*inv);
        float4 w1 = make_float4(o_acc[i][4]*inv, o_acc[i][5]*inv, o_acc[i][6]*inv, o_acc[i][7]*inv);
        go4[tok * (HIDDEN_D/4) + h * (HD/4) + tx*2]     = w0;
        go4[tok * (HIDDEN_D/4) + h * (HD/4) + tx*2 + 1] = w1;
    }
}

// =====================================================================
// Launch
// =====================================================================
extern "C" void kernel_launch(void* const* d_in, const int* in_sizes, int n_in,
                              void* d_out, int out_size)
{
    const float* hidden = (const float*)d_in[0];
    const float* Wq     = (const float*)d_in[1];
    const float* Wk     = (const float*)d_in[2];
    const float* Wv     = (const float*)d_in[3];
    const float* Wo     = (const float*)d_in[4];
    const float* kc     = (const float*)d_in[5];
    const float* vc     = (const float*)d_in[6];
    const int*   btab   = (const int*)d_in[7];
    const int*   pos    = (const int*)d_in[8];
    const int*   kvl    = (const int*)d_in[9];
    float* out = (float*)d_out;

    float *pq = nullptr, *pk = nullptr, *pv = nullptr, *po = nullptr;
    __nv_bfloat16 *pas = nullptr, *pbs = nullptr;
    cudaGetSymbolAddress((void**)&pq, g_q);
    cudaGetSymbolAddress((void**)&pk, g_k);
    cudaGetSymbolAddress((void**)&pv, g_v);
    cudaGetSymbolAddress((void**)&po, g_o);
    cudaGetSymbolAddress((void**)&pas, g_as);
    cudaGetSymbolAddress((void**)&pbs, g_bs);

    cudaFuncSetAttribute(mma_gemm_k, cudaFuncAttributeMaxDynamicSharedMemorySize, MG_SMEM);
    cudaFuncSetAttribute(attn_k, cudaFuncAttributeMaxDynamicSharedMemorySize, SMEM_BYTES);

    const dim3 gsplit_a(TOKENS * 1024 / 256), bsplit(256);
    const dim3 gsplit_w(HIDDEN_D / 32, HIDDEN_D / 32), bsplit_w(32, 8);
    const dim3 ggemm(HIDDEN_D / BN, HIDDEN_D / BM), bgemm(512);

    // A' from hidden (shared by Q/K/V GEMMs)
    split_a_k<<<gsplit_a, bsplit>>>(hidden, pas);

    split_wt_k<<<gsplit_w, bsplit_w>>>(Wq, pbs);
    mma_gemm_k<<<ggemm, bgemm, MG_SMEM>>>(pas, pbs, pq);
    split_wt_k<<<gsplit_w, bsplit_w>>>(Wk, pbs);
    mma_gemm_k<<<ggemm, bgemm, MG_SMEM>>>(pas, pbs, pk);
    split_wt_k<<<gsplit_w, bsplit_w>>>(Wv, pbs);
    mma_gemm_k<<<ggemm, bgemm, MG_SMEM>>>(pas, pbs, pv);

    rope_k<<<(TOKENS * NHEAD * 64) / 256, 256>>>(pos);

    attn_k<<<dim3(QLEN / 64, NHEAD, BATCH), 256, SMEM_BYTES>>>(kc, vc, btab, pos, kvl);

    // output projection
    split_a_k<<<gsplit_a, bsplit>>>(po, pas);
    split_wt_k<<<gsplit_w, bsplit_w>>>(Wo, pbs);
    mma_gemm_k<<<ggemm, bgemm, MG_SMEM>>>(pas, pbs, out);
}

// round 8
// speedup vs baseline: 1.9454x; 1.1307x over previous
#include <cuda_runtime.h>
#include <cuda_bf16.h>
#include <cstdint>
#include <math.h>

// ---------------- problem constants ----------------
#define TOKENS   4096      // B * Q_LEN
#define HIDDEN_D 4096
#define NHEAD    32
#define HD       128
#define QLEN     512
#define BATCH    8
#define BS64     64
#define NBLK     16

#define KSPLIT   12288     // 3 * 4096 (hi*hi | hi*lo | lo*hi)

// ---------------- scratch (device globals: no runtime alloc allowed) ----------------
__device__ float g_q[(size_t)TOKENS * HIDDEN_D];
__device__ float g_k[(size_t)TOKENS * HIDDEN_D];
__device__ float g_v[(size_t)TOKENS * HIDDEN_D];
__device__ float g_o[(size_t)TOKENS * HIDDEN_D];
__device__ __nv_bfloat16 g_as[(size_t)TOKENS * KSPLIT];    // A' = [hi | hi | lo]
__device__ __nv_bfloat16 g_bs[(size_t)HIDDEN_D * KSPLIT];  // B' = [Wt_hi | Wt_lo | Wt_hi]

// =====================================================================
// PTX helpers (baseline ISA only: ldmatrix / mma.sync / cp.async)
// =====================================================================
__device__ __forceinline__ uint32_t smem_u32(const void* p) {
    uint32_t a;
    asm("{ .reg .u64 t; cvta.to.shared.u64 t, %1; cvt.u32.u64 %0, t; }" : "=r"(a) : "l"(p));
    return a;
}
__device__ __forceinline__ void cpasync16(uint32_t s, const void* g) {
    asm volatile("cp.async.cg.shared.global [%0], [%1], 16;" :: "r"(s), "l"(g));
}
#define CP_COMMIT() asm volatile("cp.async.commit_group;" ::: "memory")
#define CP_WAIT(n)  asm volatile("cp.async.wait_group %0;" :: "n"(n) : "memory")

__device__ __forceinline__ void ldsm_x4(uint32_t* r, uint32_t addr) {
    asm volatile("ldmatrix.sync.aligned.m8n8.x4.shared.b16 {%0,%1,%2,%3}, [%4];"
        : "=r"(r[0]), "=r"(r[1]), "=r"(r[2]), "=r"(r[3]) : "r"(addr));
}
__device__ __forceinline__ void ldsm_x2(uint32_t* r, uint32_t addr) {
    asm volatile("ldmatrix.sync.aligned.m8n8.x2.shared.b16 {%0,%1}, [%2];"
        : "=r"(r[0]), "=r"(r[1]) : "r"(addr));
}
__device__ __forceinline__ void mma16816(float* c, const uint32_t* a, const uint32_t* b) {
    asm volatile("mma.sync.aligned.m16n8k16.row.col.f32.bf16.bf16.f32 "
        "{%0,%1,%2,%3}, {%4,%5,%6,%7}, {%8,%9}, {%0,%1,%2,%3};"
        : "+f"(c[0]), "+f"(c[1]), "+f"(c[2]), "+f"(c[3])
        : "r"(a[0]), "r"(a[1]), "r"(a[2]), "r"(a[3]), "r"(b[0]), "r"(b[1]));
}

union BF4 { __nv_bfloat16 b[4]; uint2 u; };
__device__ __forceinline__ void split4(float4 x, uint2& h, uint2& l) {
    float xs[4] = {x.x, x.y, x.z, x.w};
    BF4 H, L;
#pragma unroll
    for (int i = 0; i < 4; i++) {
        H.b[i] = __float2bfloat16(xs[i]);
        L.b[i] = __float2bfloat16(xs[i] - __bfloat162float(H.b[i]));
    }
    h = H.u; l = L.u;
}

// =====================================================================
// Split kernels: fp32 -> (hi, lo) bf16, arranged for K' = 3*4096 GEMM.
// =====================================================================
__global__ void split_a_k(const float* __restrict__ X, __nv_bfloat16* __restrict__ As)
{
    int idx = blockIdx.x * blockDim.x + threadIdx.x;   // < 4096*1024
    int m = idx >> 10, k4 = idx & 1023;
    float4 x = ((const float4*)X)[(size_t)m * 1024 + k4];
    uint2 h, l;
    split4(x, h, l);
    size_t base = (size_t)m * KSPLIT + k4 * 4;
    *(uint2*)(As + base)        = h;
    *(uint2*)(As + base + 4096) = h;
    *(uint2*)(As + base + 8192) = l;
}

__global__ void split_wt_k(const float* __restrict__ W, __nv_bfloat16* __restrict__ Bs)
{
    __shared__ float t[32][33];
    int n0 = blockIdx.x * 32, k0 = blockIdx.y * 32;
    int tx = threadIdx.x, ty = threadIdx.y;   // (32, 8)
#pragma unroll
    for (int i = 0; i < 4; i++)
        t[ty + i * 8][tx] = W[(size_t)(k0 + ty + i * 8) * HIDDEN_D + n0 + tx];
    __syncthreads();
#pragma unroll
    for (int i = 0; i < 4; i++) {
        int n = n0 + ty + i * 8, kk = k0 + tx;
        float x = t[tx][ty + i * 8];
        __nv_bfloat16 h = __float2bfloat16(x);
        __nv_bfloat16 l = __float2bfloat16(x - __bfloat162float(h));
        size_t base = (size_t)n * KSPLIT + kk;
        Bs[base]        = h;
        Bs[base + 4096] = l;
        Bs[base + 8192] = h;
    }
}

// =====================================================================
// HMMA GEMM: C[4096,4096] fp32 = A'[4096,K'] x B'[4096,K']^T
// CTA tile 128x256x64, 512 threads (16 warps, warp tile 64x32),
// 3-stage cp.async pipeline, smem row stride 144B (conflict-free ldmatrix).
// =====================================================================
#define BM 128
#define BN 256
#define BK 64
#define ROWB 144                      // 64 bf16 = 128B + 16B pad
#define A_STAGE (BM * ROWB)           // 18432
#define B_STAGE (BN * ROWB)           // 36864
#define STAGE_B (A_STAGE + B_STAGE)   // 55296
#define NSTAGE 3
#define MG_SMEM (STAGE_B * NSTAGE)    // 165888
#define NT_CHUNKS (KSPLIT / BK)       // 192

__global__ __launch_bounds__(512, 1)
void mma_gemm_k(const __nv_bfloat16* __restrict__ A, const __nv_bfloat16* __restrict__ Bt,
                float* __restrict__ C)
{
    extern __shared__ char smem[];
    const uint32_t sbase = smem_u32(smem);
    const int tid  = threadIdx.x;
    const int lane = tid & 31, wid = tid >> 5;
    const int warp_m = wid >> 3;          // 0..1
    const int warp_n = wid & 7;           // 0..7
    const int brow = blockIdx.y * BM;
    const int bcol = blockIdx.x * BN;

    float acc[4][4][4];
#pragma unroll
    for (int i = 0; i < 4; i++)
#pragma unroll
        for (int j = 0; j < 4; j++)
#pragma unroll
            for (int q = 0; q < 4; q++) acc[i][j][q] = 0.f;

    // per-stage load: A 1024 16B-chunks (2/thread), B 2048 (4/thread)
#define LOAD_STAGE(st, kc) do {                                                        \
    uint32_t sA = sbase + (st) * STAGE_B;                                              \
    uint32_t sB = sA + A_STAGE;                                                        \
    _Pragma("unroll")                                                                  \
    for (int u = 0; u < 2; u++) {                                                      \
        int e = tid + u * 512, r = e >> 3, c = e & 7;                                  \
        cpasync16(sA + r * ROWB + c * 16, A + (size_t)(brow + r) * KSPLIT + (kc) + c * 8); \
    }                                                                                  \
    _Pragma("unroll")                                                                  \
    for (int u = 0; u < 4; u++) {                                                      \
        int e = tid + u * 512, r = e >> 3, c = e & 7;                                  \
        cpasync16(sB + r * ROWB + c * 16, Bt + (size_t)(bcol + r) * KSPLIT + (kc) + c * 8); \
    }                                                                                  \
} while (0)

    LOAD_STAGE(0, 0);  CP_COMMIT();
    LOAD_STAGE(1, BK); CP_COMMIT();

    const uint32_t a_row = (uint32_t)(warp_m * 64 + (lane & 15));
    const uint32_t a_kh  = (uint32_t)(((lane >> 4) << 3) * 2);      // byte
    const uint32_t b_row = (uint32_t)(warp_n * 32 + (lane & 7));
    const uint32_t b_kh  = (uint32_t)((((lane >> 3) & 1) << 3) * 2);

    for (int t = 0; t < NT_CHUNKS; t++) {
        CP_WAIT(1);
        __syncthreads();
        if (t + 2 < NT_CHUNKS) LOAD_STAGE((t + 2) % NSTAGE, (t + 2) * BK);
        CP_COMMIT();

        const uint32_t sA = sbase + (t % NSTAGE) * STAGE_B;
        const uint32_t sB = sA + A_STAGE;

#pragma unroll
        for (int ks = 0; ks < 4; ks++) {
            uint32_t af[4][4], bfr[4][2];
            const uint32_t kb = (uint32_t)(ks * 32);   // 16 bf16 = 32 bytes
#pragma unroll
            for (int i = 0; i < 4; i++)
                ldsm_x4(af[i], sA + (a_row + i * 16) * ROWB + kb + a_kh);
#pragma unroll
            for (int j = 0; j < 4; j++)
                ldsm_x2(bfr[j], sB + (b_row + j * 8) * ROWB + kb + b_kh);
#pragma unroll
            for (int i = 0; i < 4; i++)
#pragma unroll
                for (int j = 0; j < 4; j++)
                    mma16816(acc[i][j], af[i], bfr[j]);
        }
    }
#undef LOAD_STAGE

    // epilogue
#pragma unroll
    for (int i = 0; i < 4; i++) {
        int row0 = brow + warp_m * 64 + i * 16 + (lane >> 2);
#pragma unroll
        for (int j = 0; j < 4; j++) {
            int col = bcol + warp_n * 32 + j * 8 + (lane & 3) * 2;
            *(float2*)(C + (size_t)row0 * HIDDEN_D + col)       = make_float2(acc[i][j][0], acc[i][j][1]);
            *(float2*)(C + (size_t)(row0 + 8) * HIDDEN_D + col) = make_float2(acc[i][j][2], acc[i][j][3]);
        }
    }
}

// =====================================================================
// RoPE (in-place on g_q, g_k).
// =====================================================================
__global__ void rope_k(const int* __restrict__ pos)
{
    int idx = blockIdx.x * blockDim.x + threadIdx.x;
    if (idx >= TOKENS * NHEAD * 64) return;
    int d   = idx & 63;
    int th  = idx >> 6;
    int tok = th >> 5;
    float p = (float)pos[tok];
    float f = p * exp2f(-0.207620505930454f * (float)d);  // log2(10000)/64
    float s, c;
    sincosf(f, &s, &c);
    size_t base = (size_t)th * HD;
    float x1 = g_q[base + d], x2 = g_q[base + d + 64];
    g_q[base + d]      = x1 * c - x2 * s;
    g_q[base + d + 64] = x2 * c + x1 * s;
    x1 = g_k[base + d]; x2 = g_k[base + d + 64];
    g_k[base + d]      = x1 * c - x2 * s;
    g_k[base + d + 64] = x2 * c + x1 * s;
}

// =====================================================================
// Flash attention over paged KV; QK^T via HMMA (3-term bf16 split),
// softmax + P@V stay SIMT fp32.
// 256 threads = 8 warps; Q tile 64x128, KV tiles 64 rows.
// =====================================================================
#define ATROWB 272          // bf16 tile row: 128 bf16 = 256B + 16B pad
#define VS_STRIDE4 33       // fp32 V: 132 floats
#define SS_STRIDE 65

// byte offsets in dynamic smem
#define AT_QH   0
#define AT_QL   17408
#define AT_KH   34816
#define AT_KL   52224
#define AT_VS   69632                   // fp32 64x132 = 33792
#define AT_SS   (AT_VS + 33792)         // 103424, fp32 64x65
#define AT_PMAX (AT_SS + 16640)         // 120064
#define AT_PSUM (AT_PMAX + 4096)        // 124160
#define AT_M    (AT_PSUM + 4096)        // 128256
#define AT_L    (AT_M + 256)
#define AT_SC   (AT_L + 256)
#define AT_SMEM (AT_SC + 256)           // 129024 B

__global__ __launch_bounds__(256, 1)
void attn_k(const float* __restrict__ kcache, const float* __restrict__ vcache,
            const int* __restrict__ btab, const int* __restrict__ pos,
            const int* __restrict__ kvlen_arr)
{
    extern __shared__ char smem[];
    const uint32_t sb = smem_u32(smem);
    float* Vs   = (float*)(smem + AT_VS);
    float* Ss   = (float*)(smem + AT_SS);
    float* pmax = (float*)(smem + AT_PMAX);
    float* psum = (float*)(smem + AT_PSUM);
    float* mrow = (float*)(smem + AT_M);
    float* lrow = (float*)(smem + AT_L);
    float* srow = (float*)(smem + AT_SC);

    const int qt = blockIdx.x, h = blockIdx.y, b = blockIdx.z;
    const int tid = threadIdx.x;
    const int tx = tid & 15, ty = tid >> 4;
    const int lane = tid & 31, wid = tid >> 5;
    const int wm = wid & 3, wn = wid >> 2;   // warp grid 4(m) x 2(n)
    const int kvlen = kvlen_arr[b];
    const int tok0  = b * QLEN + qt * 64;
    const int qpos0 = pos[tok0];

    // ---- load Q tile, split to hi/lo bf16 smem ----
    const float4* gq4 = (const float4*)g_q;
    for (int i = tid; i < 2048; i += 256) {
        int r = i >> 5, c4 = i & 31;
        float4 qv = gq4[((size_t)(tok0 + r) * NHEAD + h) * (HD/4) + c4];
        uint2 hh, ll;
        split4(qv, hh, ll);
        uint32_t off = (uint32_t)(r * ATROWB + c4 * 8);
        *(uint2*)(smem + AT_QH + off) = hh;
        *(uint2*)(smem + AT_QL + off) = ll;
    }
    if (tid < 64) { mrow[tid] = -3.0e38f; lrow[tid] = 0.f; }

    float o_acc[4][8];
#pragma unroll
    for (int i = 0; i < 4; i++)
#pragma unroll
        for (int c = 0; c < 8; c++) o_acc[i][c] = 0.f;

    int tmax = (qpos0 + 63) >> 6;
    int tkv  = (kvlen - 1) >> 6;
    if (tmax > tkv) tmax = tkv;
    if (tmax > NBLK - 1) tmax = NBLK - 1;

    const float scl = 0.0883883476483184f;   // 1/sqrt(128)

    // ldmatrix lane address components
    const uint32_t qrow_b = (uint32_t)((wm * 16 + (lane & 15)) * ATROWB);
    const uint32_t q_kh   = (uint32_t)(((lane >> 4) << 3) * 2);
    const uint32_t k_kh   = (uint32_t)((((lane >> 3) & 1) << 3) * 2);

    for (int t = 0; t <= tmax; t++) {
        const float* ksrc; const float* vsrc;
        if (t < 8) {
            int pb = btab[b * NBLK + t];
            size_t base = ((size_t)pb * BS64 * NHEAD + h) * HD;
            ksrc = kcache + base; vsrc = vcache + base;
        } else {
            int tokk = b * QLEN + (t - 8) * 64;
            size_t base = ((size_t)tokk * NHEAD + h) * HD;
            ksrc = g_k + base; vsrc = g_v + base;
        }
        __syncthreads();  // previous tile's consumers done before overwrite

        // ---- load K (split hi/lo bf16) + V (fp32) ----
        for (int i = tid; i < 2048; i += 256) {
            int r = i >> 5, c4 = i & 31;
            float4 kv4 = *(const float4*)(ksrc + (size_t)r * (NHEAD*HD) + c4*4);
            uint2 hh, ll;
            split4(kv4, hh, ll);
            uint32_t off = (uint32_t)(r * ATROWB + c4 * 8);
            *(uint2*)(smem + AT_KH + off) = hh;
            *(uint2*)(smem + AT_KL + off) = ll;
            float4 vv4 = *(const float4*)(vsrc + (size_t)r * (NHEAD*HD) + c4*4);
            ((float4*)Vs)[r * VS_STRIDE4 + c4] = vv4;
        }
        __syncthreads();

        // ---- S = Q K^T via HMMA, 3 terms: qh*kh + qh*kl + ql*kh ----
        {
            float sc4[4][4];
#pragma unroll
            for (int j = 0; j < 4; j++)
#pragma unroll
                for (int q = 0; q < 4; q++) sc4[j][q] = 0.f;

            const uint32_t qb_t[3] = { sb + AT_QH, sb + AT_QH, sb + AT_QL };
            const uint32_t kb_t[3] = { sb + AT_KH, sb + AT_KL, sb + AT_KH };
#pragma unroll
            for (int tm = 0; tm < 3; tm++) {
                const uint32_t qb = qb_t[tm], kb = kb_t[tm];
#pragma unroll
                for (int kc = 0; kc < 8; kc++) {
                    uint32_t af[4];
                    ldsm_x4(af, qb + qrow_b + kc * 32 + q_kh);
#pragma unroll
                    for (int j = 0; j < 4; j++) {
                        uint32_t bf2[2];
                        ldsm_x2(bf2, kb + (uint32_t)((wn * 32 + j * 8 + (lane & 7)) * ATROWB) + kc * 32 + k_kh);
                        mma16816(sc4[j], af, bf2);
                    }
                }
            }
            // store fragments to Ss (raw scores)
            const int r0 = wm * 16 + (lane >> 2);
            const int c0 = wn * 32 + (lane & 3) * 2;
#pragma unroll
            for (int j = 0; j < 4; j++) {
                Ss[r0 * SS_STRIDE + c0 + j * 8]           = sc4[j][0];
                Ss[r0 * SS_STRIDE + c0 + j * 8 + 1]       = sc4[j][1];
                Ss[(r0 + 8) * SS_STRIDE + c0 + j * 8]     = sc4[j][2];
                Ss[(r0 + 8) * SS_STRIDE + c0 + j * 8 + 1] = sc4[j][3];
            }
        }
        __syncthreads();

        // ---- scale + causal mask + per-thread row max (reads/writes own 4x4) ----
        const int kvbase = t * 64 + tx * 4;
#pragma unroll
        for (int i = 0; i < 4; i++) {
            int r = ty * 4 + i;
            int qp = qpos0 + r;
            float pm = -3.0e38f;
#pragma unroll
            for (int j = 0; j < 4; j++) {
                float sv = Ss[r * SS_STRIDE + tx*4 + j] * scl;
                int kvp = kvbase + j;
                if (kvp > qp || kvp >= kvlen) sv = -3.0e38f;
                Ss[r * SS_STRIDE + tx*4 + j] = sv;
                pm = fmaxf(pm, sv);
            }
            pmax[r * 16 + tx] = pm;
        }
        __syncthreads();

        // ---- online-softmax row state (64 threads) ----
        if (tid < 64) {
            float m0 = mrow[tid];
            float tm = -3.0e38f;
#pragma unroll
            for (int u = 0; u < 16; u++) tm = fmaxf(tm, pmax[tid*16 + u]);
            float mn = fmaxf(m0, tm);
            float sc = __expf(m0 - mn);
            srow[tid] = sc;
            mrow[tid] = mn;
            lrow[tid] *= sc;
        }
        __syncthreads();

        // ---- exp pass + partial sums + rescale O ----
#pragma unroll
        for (int i = 0; i < 4; i++) {
            int r = ty*4 + i;
            float mr = mrow[r];
            float s = 0.f;
#pragma unroll
            for (int j = 0; j < 4; j++) {
                float pv = __expf(Ss[r * SS_STRIDE + tx*4 + j] - mr);
                Ss[r * SS_STRIDE + tx*4 + j] = pv;
                s += pv;
            }
            psum[r * 16 + tx] = s;
            float sc = srow[r];
#pragma unroll
            for (int c = 0; c < 8; c++) o_acc[i][c] *= sc;
        }
        __syncthreads();

        if (tid < 64) {
            float s = 0.f;
#pragma unroll
            for (int u = 0; u < 16; u++) s += psum[tid*16 + u];
            lrow[tid] += s;
        }

        // ---- O += P @ V (SIMT fp32) ----
        const float4* vsv = (const float4*)Vs;
#pragma unroll 4
        for (int j = 0; j < 64; j++) {
            float4 v0 = vsv[j * VS_STRIDE4 + tx*2];
            float4 v1 = vsv[j * VS_STRIDE4 + tx*2 + 1];
            float p0 = Ss[(ty*4 + 0) * SS_STRIDE + j];
            float p1 = Ss[(ty*4 + 1) * SS_STRIDE + j];
            float p2 = Ss[(ty*4 + 2) * SS_STRIDE + j];
            float p3 = Ss[(ty*4 + 3) * SS_STRIDE + j];
            o_acc[0][0] += p0*v0.x; o_acc[0][1] += p0*v0.y; o_acc[0][2] += p0*v0.z; o_acc[0][3] += p0*v0.w;
            o_acc[0][4] += p0*v1.x; o_acc[0][5] += p0*v1.y; o_acc[0][6] += p0*v1.z; o_acc[0][7] += p0*v1.w;
            o_acc[1][0] += p1*v0.x; o_acc[1][1] += p1*v0.y; o_acc[1][2] += p1*v0.z; o_acc[1][3] += p1*v0.w;
            o_acc[1][4] += p1*v1.x; o_acc[1][5] += p1*v1.y; o_acc[1][6] += p1*v1.z; o_acc[1][7] += p1*v1.w;
            o_acc[2][0] += p2*v0.x; o_acc[2][1] += p2*v0.y; o_acc[2][2] += p2*v0.z; o_acc[2][3] += p2*v0.w;
            o_acc[2][4] += p2*v1.x; o_acc[2][5] += p2*v1.y; o_acc[2][6] += p2*v1.z; o_acc[2][7] += p2*v1.w;
            o_acc[3][0] += p3*v0.x; o_acc[3][1] += p3*v0.y; o_acc[3][2] += p3*v0.z; o_acc[3][3] += p3*v0.w;
            o_acc[3][4] += p3*v1.x; o_acc[3][5] += p3*v1.y; o_acc[3][6] += p3*v1.z; o_acc[3][7] += p3*v1.w;
        }
    }
    __syncthreads();

    // ---- normalize + write to g_o [tok][head][hd] ----
    float4* go4 = (float4*)g_o;
#pragma unroll
    for (int i = 0; i < 4; i++) {
        int r = ty*4 + i;
        float inv = 1.f / lrow[r];
        size_t tok = (size_t)tok0 + r;
        float4 w0 = make_float4(o_acc[i][0]*inv, o_acc[i][1]*inv, o_acc[i][2]*inv, o_acc[i][3]*inv);
        float4 w1 = make_float4(o_acc[i][4]*inv, o_acc[i][5]*inv, o_acc[i][6]*inv, o_acc[i][7]*inv);
        go4[tok * (HIDDEN_D/4) + h * (HD/4) + tx*2]     = w0;
        go4[tok * (HIDDEN_D/4) + h * (HD/4) + tx*2 + 1] = w1;
    }
}

// =====================================================================
// Launch
// =====================================================================
extern "C" void kernel_launch(void* const* d_in, const int* in_sizes, int n_in,
                              void* d_out, int out_size)
{
    const float* hidden = (const float*)d_in[0];
    const float* Wq     = (const float*)d_in[1];
    const float* Wk     = (const float*)d_in[2];
    const float* Wv     = (const float*)d_in[3];
    const float* Wo     = (const float*)d_in[4];
    const float* kc     = (const float*)d_in[5];
    const float* vc     = (const float*)d_in[6];
    const int*   btab   = (const int*)d_in[7];
    const int*   pos    = (const int*)d_in[8];
    const int*   kvl    = (const int*)d_in[9];
    float* out = (float*)d_out;

    float *pq = nullptr, *pk = nullptr, *pv = nullptr, *po = nullptr;
    __nv_bfloat16 *pas = nullptr, *pbs = nullptr;
    cudaGetSymbolAddress((void**)&pq, g_q);
    cudaGetSymbolAddress((void**)&pk, g_k);
    cudaGetSymbolAddress((void**)&pv, g_v);
    cudaGetSymbolAddress((void**)&po, g_o);
    cudaGetSymbolAddress((void**)&pas, g_as);
    cudaGetSymbolAddress((void**)&pbs, g_bs);

    cudaFuncSetAttribute(mma_gemm_k, cudaFuncAttributeMaxDynamicSharedMemorySize, MG_SMEM);
    cudaFuncSetAttribute(attn_k, cudaFuncAttributeMaxDynamicSharedMemorySize, AT_SMEM);

    const dim3 gsplit_a(TOKENS * 1024 / 256), bsplit(256);
    const dim3 gsplit_w(HIDDEN_D / 32, HIDDEN_D / 32), bsplit_w(32, 8);
    const dim3 ggemm(HIDDEN_D / BN, HIDDEN_D / BM), bgemm(512);

    // A' from hidden (shared by Q/K/V GEMMs)
    split_a_k<<<gsplit_a, bsplit>>>(hidden, pas);

    split_wt_k<<<gsplit_w, bsplit_w>>>(Wq, pbs);
    mma_gemm_k<<<ggemm, bgemm, MG_SMEM>>>(pas, pbs, pq);
    split_wt_k<<<gsplit_w, bsplit_w>>>(Wk, pbs);
    mma_gemm_k<<<ggemm, bgemm, MG_SMEM>>>(pas, pbs, pk);
    split_wt_k<<<gsplit_w, bsplit_w>>>(Wv, pbs);
    mma_gemm_k<<<ggemm, bgemm, MG_SMEM>>>(pas, pbs, pv);

    rope_k<<<(TOKENS * NHEAD * 64) / 256, 256>>>(pos);

    attn_k<<<dim3(QLEN / 64, NHEAD, BATCH), 256, AT_SMEM>>>(kc, vc, btab, pos, kvl);

    // output projection
    split_a_k<<<gsplit_a, bsplit>>>(po, pas);
    split_wt_k<<<gsplit_w, bsplit_w>>>(Wo, pbs);
    mma_gemm_k<<<ggemm, bgemm, MG_SMEM>>>(pas, pbs, out);
}

// round 9
// speedup vs baseline: 2.3471x; 1.2065x over previous
#include <cuda_runtime.h>
#include <cuda_bf16.h>
#include <cstdint>
#include <math.h>

// ---------------- problem constants ----------------
#define TOKENS   4096      // B * Q_LEN
#define HIDDEN_D 4096
#define NHEAD    32
#define HD       128
#define QLEN     512
#define BATCH    8
#define BS64     64
#define NBLK     16

#define KSPLIT   12288     // 3 * 4096 (hi*hi | hi*lo | lo*hi)
#define NQKV     12288     // fused QKV output columns

// ---------------- scratch (device globals: no runtime alloc allowed) ----------------
__device__ float g_q[(size_t)TOKENS * HIDDEN_D];
__device__ float g_k[(size_t)TOKENS * HIDDEN_D];
__device__ float g_v[(size_t)TOKENS * HIDDEN_D];
__device__ float g_o[(size_t)TOKENS * HIDDEN_D];
__device__ __nv_bfloat16 g_as[(size_t)TOKENS * KSPLIT];     // A' = [hi | hi | lo]
__device__ __nv_bfloat16 g_bs3[(size_t)NQKV * KSPLIT];      // B' rows for Wq|Wk|Wv (or Wo)

// =====================================================================
// PTX helpers (baseline ISA only: ldmatrix / mma.sync / cp.async)
// =====================================================================
__device__ __forceinline__ uint32_t smem_u32(const void* p) {
    uint32_t a;
    asm("{ .reg .u64 t; cvta.to.shared.u64 t, %1; cvt.u32.u64 %0, t; }" : "=r"(a) : "l"(p));
    return a;
}
__device__ __forceinline__ void cpasync16(uint32_t s, const void* g) {
    asm volatile("cp.async.cg.shared.global [%0], [%1], 16;" :: "r"(s), "l"(g));
}
#define CP_COMMIT() asm volatile("cp.async.commit_group;" ::: "memory")
#define CP_WAIT(n)  asm volatile("cp.async.wait_group %0;" :: "n"(n) : "memory")

__device__ __forceinline__ void ldsm_x4(uint32_t* r, uint32_t addr) {
    asm volatile("ldmatrix.sync.aligned.m8n8.x4.shared.b16 {%0,%1,%2,%3}, [%4];"
        : "=r"(r[0]), "=r"(r[1]), "=r"(r[2]), "=r"(r[3]) : "r"(addr));
}
__device__ __forceinline__ void ldsm_x2(uint32_t* r, uint32_t addr) {
    asm volatile("ldmatrix.sync.aligned.m8n8.x2.shared.b16 {%0,%1}, [%2];"
        : "=r"(r[0]), "=r"(r[1]) : "r"(addr));
}
__device__ __forceinline__ void ldsm_x2t(uint32_t* r, uint32_t addr) {
    asm volatile("ldmatrix.sync.aligned.m8n8.x2.trans.shared.b16 {%0,%1}, [%2];"
        : "=r"(r[0]), "=r"(r[1]) : "r"(addr));
}
__device__ __forceinline__ void mma16816(float* c, const uint32_t* a, const uint32_t* b) {
    asm volatile("mma.sync.aligned.m16n8k16.row.col.f32.bf16.bf16.f32 "
        "{%0,%1,%2,%3}, {%4,%5,%6,%7}, {%8,%9}, {%0,%1,%2,%3};"
        : "+f"(c[0]), "+f"(c[1]), "+f"(c[2]), "+f"(c[3])
        : "r"(a[0]), "r"(a[1]), "r"(a[2]), "r"(a[3]), "r"(b[0]), "r"(b[1]));
}

union BF4 { __nv_bfloat16 b[4]; uint2 u; };
__device__ __forceinline__ void split4(float4 x, uint2& h, uint2& l) {
    float xs[4] = {x.x, x.y, x.z, x.w};
    BF4 H, L;
#pragma unroll
    for (int i = 0; i < 4; i++) {
        H.b[i] = __float2bfloat16(xs[i]);
        L.b[i] = __float2bfloat16(xs[i] - __bfloat162float(H.b[i]));
    }
    h = H.u; l = L.u;
}

// =====================================================================
// Split kernels: fp32 -> (hi, lo) bf16, arranged for K' = 3*4096 GEMM.
// =====================================================================
__global__ void split_a_k(const float* __restrict__ X, __nv_bfloat16* __restrict__ As)
{
    int idx = blockIdx.x * blockDim.x + threadIdx.x;   // < 4096*1024
    int m = idx >> 10, k4 = idx & 1023;
    float4 x = ((const float4*)X)[(size_t)m * 1024 + k4];
    uint2 h, l;
    split4(x, h, l);
    size_t base = (size_t)m * KSPLIT + k4 * 4;
    *(uint2*)(As + base)        = h;
    *(uint2*)(As + base + 4096) = h;
    *(uint2*)(As + base + 8192) = l;
}

__global__ void split_wt_k(const float* __restrict__ W, __nv_bfloat16* __restrict__ Bs)
{
    __shared__ float t[32][33];
    int n0 = blockIdx.x * 32, k0 = blockIdx.y * 32;
    int tx = threadIdx.x, ty = threadIdx.y;   // (32, 8)
#pragma unroll
    for (int i = 0; i < 4; i++)
        t[ty + i * 8][tx] = W[(size_t)(k0 + ty + i * 8) * HIDDEN_D + n0 + tx];
    __syncthreads();
#pragma unroll
    for (int i = 0; i < 4; i++) {
        int n = n0 + ty + i * 8, kk = k0 + tx;
        float x = t[tx][ty + i * 8];
        __nv_bfloat16 h = __float2bfloat16(x);
        __nv_bfloat16 l = __float2bfloat16(x - __bfloat162float(h));
        size_t base = (size_t)n * KSPLIT + kk;
        Bs[base]        = h;
        Bs[base + 4096] = l;
        Bs[base + 8192] = h;
    }
}

// =====================================================================
// HMMA GEMM: C[4096, N] fp32 = A'[4096,K'] x B'[N,K']^T   (N = gridDim.x*256)
// Epilogue routes each 4096-column block to C0/C1/C2 (fused QKV).
// CTA tile 128x256x64, 512 threads, 4-stage cp.async pipeline.
// =====================================================================
#define BM 128
#define BN 256
#define BK 64
#define ROWB 144                      // 64 bf16 = 128B + 16B pad
#define A_STAGE (BM * ROWB)           // 18432
#define B_STAGE (BN * ROWB)           // 36864
#define STAGE_B (A_STAGE + B_STAGE)   // 55296
#define NSTAGE 4
#define MG_SMEM (STAGE_B * NSTAGE)    // 221184
#define NT_CHUNKS (KSPLIT / BK)       // 192

__global__ __launch_bounds__(512, 1)
void mma_gemm_k(const __nv_bfloat16* __restrict__ A, const __nv_bfloat16* __restrict__ Bt,
                float* __restrict__ C0, float* __restrict__ C1, float* __restrict__ C2)
{
    extern __shared__ char smem[];
    const uint32_t sbase = smem_u32(smem);
    const int tid  = threadIdx.x;
    const int lane = tid & 31, wid = tid >> 5;
    const int warp_m = wid >> 3;          // 0..1
    const int warp_n = wid & 7;           // 0..7
    const int brow = blockIdx.y * BM;
    const int bcol = blockIdx.x * BN;

    float acc[4][4][4];
#pragma unroll
    for (int i = 0; i < 4; i++)
#pragma unroll
        for (int j = 0; j < 4; j++)
#pragma unroll
            for (int q = 0; q < 4; q++) acc[i][j][q] = 0.f;

#define LOAD_STAGE(st, kc) do {                                                        \
    uint32_t sA = sbase + (st) * STAGE_B;                                              \
    uint32_t sB = sA + A_STAGE;                                                        \
    _Pragma("unroll")                                                                  \
    for (int u = 0; u < 2; u++) {                                                      \
        int e = tid + u * 512, r = e >> 3, c = e & 7;                                  \
        cpasync16(sA + r * ROWB + c * 16, A + (size_t)(brow + r) * KSPLIT + (kc) + c * 8); \
    }                                                                                  \
    _Pragma("unroll")                                                                  \
    for (int u = 0; u < 4; u++) {                                                      \
        int e = tid + u * 512, r = e >> 3, c = e & 7;                                  \
        cpasync16(sB + r * ROWB + c * 16, Bt + (size_t)(bcol + r) * KSPLIT + (kc) + c * 8); \
    }                                                                                  \
} while (0)

    LOAD_STAGE(0, 0);      CP_COMMIT();
    LOAD_STAGE(1, BK);     CP_COMMIT();
    LOAD_STAGE(2, 2 * BK); CP_COMMIT();

    const uint32_t a_row = (uint32_t)(warp_m * 64 + (lane & 15));
    const uint32_t a_kh  = (uint32_t)(((lane >> 4) << 3) * 2);      // byte
    const uint32_t b_row = (uint32_t)(warp_n * 32 + (lane & 7));
    const uint32_t b_kh  = (uint32_t)((((lane >> 3) & 1) << 3) * 2);

    for (int t = 0; t < NT_CHUNKS; t++) {
        CP_WAIT(2);
        __syncthreads();
        if (t + 3 < NT_CHUNKS) LOAD_STAGE((t + 3) % NSTAGE, (t + 3) * BK);
        CP_COMMIT();

        const uint32_t sA = sbase + (t % NSTAGE) * STAGE_B;
        const uint32_t sB = sA + A_STAGE;

#pragma unroll
        for (int ks = 0; ks < 4; ks++) {
            uint32_t af[4][4], bfr[4][2];
            const uint32_t kb = (uint32_t)(ks * 32);   // 16 bf16 = 32 bytes
#pragma unroll
            for (int i = 0; i < 4; i++)
                ldsm_x4(af[i], sA + (a_row + i * 16) * ROWB + kb + a_kh);
#pragma unroll
            for (int j = 0; j < 4; j++)
                ldsm_x2(bfr[j], sB + (b_row + j * 8) * ROWB + kb + b_kh);
#pragma unroll
            for (int i = 0; i < 4; i++)
#pragma unroll
                for (int j = 0; j < 4; j++)
                    mma16816(acc[i][j], af[i], bfr[j]);
        }
    }
#undef LOAD_STAGE

    // epilogue: route 4096-col block to the right output
    const int sub = bcol >> 12;
    float* C = (sub == 0) ? C0 : ((sub == 1) ? C1 : C2);
    const int bcolL = bcol & 4095;
#pragma unroll
    for (int i = 0; i < 4; i++) {
        int row0 = brow + warp_m * 64 + i * 16 + (lane >> 2);
#pragma unroll
        for (int j = 0; j < 4; j++) {
            int col = bcolL + warp_n * 32 + j * 8 + (lane & 3) * 2;
            *(float2*)(C + (size_t)row0 * HIDDEN_D + col)       = make_float2(acc[i][j][0], acc[i][j][1]);
            *(float2*)(C + (size_t)(row0 + 8) * HIDDEN_D + col) = make_float2(acc[i][j][2], acc[i][j][3]);
        }
    }
}

// =====================================================================
// RoPE (in-place on g_q, g_k).
// =====================================================================
__global__ void rope_k(const int* __restrict__ pos)
{
    int idx = blockIdx.x * blockDim.x + threadIdx.x;
    if (idx >= TOKENS * NHEAD * 64) return;
    int d   = idx & 63;
    int th  = idx >> 6;
    int tok = th >> 5;
    float p = (float)pos[tok];
    float f = p * exp2f(-0.207620505930454f * (float)d);  // log2(10000)/64
    float s, c;
    sincosf(f, &s, &c);
    size_t base = (size_t)th * HD;
    float x1 = g_q[base + d], x2 = g_q[base + d + 64];
    g_q[base + d]      = x1 * c - x2 * s;
    g_q[base + d + 64] = x2 * c + x1 * s;
    x1 = g_k[base + d]; x2 = g_k[base + d + 64];
    g_k[base + d]      = x1 * c - x2 * s;
    g_k[base + d + 64] = x2 * c + x1 * s;
}

// =====================================================================
// Flash attention: QK^T and P@V both via HMMA (3-term bf16 splits),
// softmax SIMT fp32. 256 threads = 8 warps (warp grid 4m x 2n).
// =====================================================================
#define ATROWB 272          // 128 bf16 = 256B + 16B pad
#define PROWB  144          // 64 bf16 = 128B + 16B pad
#define SS_STRIDE 65

#define AT_QH   0
#define AT_QL   17408
#define AT_KH   34816
#define AT_KL   52224
#define AT_VH   69632
#define AT_VL   87040
#define AT_SS   104448                  // fp32 64x65 = 16640
#define AT_PH   121088                  // bf16 64x(144B) = 9216
#define AT_PL   130304
#define AT_PMAX 139520                  // 4096
#define AT_PSUM 143616                  // 4096
#define AT_M    147712
#define AT_L    147968
#define AT_SC   148224
#define AT_SMEM 148480

__global__ __launch_bounds__(256, 1)
void attn_k(const float* __restrict__ kcache, const float* __restrict__ vcache,
            const int* __restrict__ btab, const int* __restrict__ pos,
            const int* __restrict__ kvlen_arr)
{
    extern __shared__ char smem[];
    const uint32_t sb = smem_u32(smem);
    float* Ss   = (float*)(smem + AT_SS);
    float* pmax = (float*)(smem + AT_PMAX);
    float* psum = (float*)(smem + AT_PSUM);
    float* mrow = (float*)(smem + AT_M);
    float* lrow = (float*)(smem + AT_L);
    float* srow = (float*)(smem + AT_SC);

    const int qt = blockIdx.x, h = blockIdx.y, b = blockIdx.z;
    const int tid = threadIdx.x;
    const int tx = tid & 15, ty = tid >> 4;
    const int lane = tid & 31, wid = tid >> 5;
    const int wm = wid & 3, wn = wid >> 2;   // warp grid 4(m) x 2(n)
    const int kvlen = kvlen_arr[b];
    const int tok0  = b * QLEN + qt * 64;
    const int qpos0 = pos[tok0];

    // ---- load Q tile, split hi/lo bf16 ----
    const float4* gq4 = (const float4*)g_q;
    for (int i = tid; i < 2048; i += 256) {
        int r = i >> 5, c4 = i & 31;
        float4 qv = gq4[((size_t)(tok0 + r) * NHEAD + h) * (HD/4) + c4];
        uint2 hh, ll;
        split4(qv, hh, ll);
        uint32_t off = (uint32_t)(r * ATROWB + c4 * 8);
        *(uint2*)(smem + AT_QH + off) = hh;
        *(uint2*)(smem + AT_QL + off) = ll;
    }
    if (tid < 64) { mrow[tid] = -3.0e38f; lrow[tid] = 0.f; }

    // O accumulator fragments: per warp m16 x n64 -> 8 n8-tiles x 4 floats
    float o_acc[8][4];
#pragma unroll
    for (int j = 0; j < 8; j++)
#pragma unroll
        for (int q = 0; q < 4; q++) o_acc[j][q] = 0.f;

    int tmax = (qpos0 + 63) >> 6;
    int tkv  = (kvlen - 1) >> 6;
    if (tmax > tkv) tmax = tkv;
    if (tmax > NBLK - 1) tmax = NBLK - 1;

    const float scl = 0.0883883476483184f;   // 1/sqrt(128)

    const uint32_t qrow_b = (uint32_t)((wm * 16 + (lane & 15)) * ATROWB);
    const uint32_t q_kh   = (uint32_t)(((lane >> 4) << 3) * 2);
    const uint32_t k_kh   = (uint32_t)((((lane >> 3) & 1) << 3) * 2);
    const uint32_t prow_b = (uint32_t)((wm * 16 + (lane & 15)) * PROWB);
    const int fr0 = wm * 16 + (lane >> 2);   // frag row (and +8)

    for (int t = 0; t <= tmax; t++) {
        const float* ksrc; const float* vsrc;
        if (t < 8) {
            int pb = btab[b * NBLK + t];
            size_t base = ((size_t)pb * BS64 * NHEAD + h) * HD;
            ksrc = kcache + base; vsrc = vcache + base;
        } else {
            int tokk = b * QLEN + (t - 8) * 64;
            size_t base = ((size_t)tokk * NHEAD + h) * HD;
            ksrc = g_k + base; vsrc = g_v + base;
        }
        __syncthreads();  // previous tile fully consumed before overwrite

        // ---- load K and V, split hi/lo bf16 ----
        for (int i = tid; i < 2048; i += 256) {
            int r = i >> 5, c4 = i & 31;
            uint32_t off = (uint32_t)(r * ATROWB + c4 * 8);
            float4 kv4 = *(const float4*)(ksrc + (size_t)r * (NHEAD*HD) + c4*4);
            uint2 hh, ll;
            split4(kv4, hh, ll);
            *(uint2*)(smem + AT_KH + off) = hh;
            *(uint2*)(smem + AT_KL + off) = ll;
            float4 vv4 = *(const float4*)(vsrc + (size_t)r * (NHEAD*HD) + c4*4);
            split4(vv4, hh, ll);
            *(uint2*)(smem + AT_VH + off) = hh;
            *(uint2*)(smem + AT_VL + off) = ll;
        }
        __syncthreads();

        // ---- S = Q K^T via HMMA: qh*kh + qh*kl + ql*kh ----
        {
            float sc4[4][4];
#pragma unroll
            for (int j = 0; j < 4; j++)
#pragma unroll
                for (int q = 0; q < 4; q++) sc4[j][q] = 0.f;

            const uint32_t qb_t[3] = { sb + AT_QH, sb + AT_QH, sb + AT_QL };
            const uint32_t kb_t[3] = { sb + AT_KH, sb + AT_KL, sb + AT_KH };
#pragma unroll
            for (int tm = 0; tm < 3; tm++) {
                const uint32_t qb = qb_t[tm], kb = kb_t[tm];
#pragma unroll
                for (int kc = 0; kc < 8; kc++) {
                    uint32_t af[4];
                    ldsm_x4(af, qb + qrow_b + kc * 32 + q_kh);
#pragma unroll
                    for (int j = 0; j < 4; j++) {
                        uint32_t bf2[2];
                        ldsm_x2(bf2, kb + (uint32_t)((wn * 32 + j * 8 + (lane & 7)) * ATROWB) + kc * 32 + k_kh);
                        mma16816(sc4[j], af, bf2);
                    }
                }
            }
            const int c0 = wn * 32 + (lane & 3) * 2;
#pragma unroll
            for (int j = 0; j < 4; j++) {
                Ss[fr0 * SS_STRIDE + c0 + j * 8]           = sc4[j][0];
                Ss[fr0 * SS_STRIDE + c0 + j * 8 + 1]       = sc4[j][1];
                Ss[(fr0 + 8) * SS_STRIDE + c0 + j * 8]     = sc4[j][2];
                Ss[(fr0 + 8) * SS_STRIDE + c0 + j * 8 + 1] = sc4[j][3];
            }
        }
        __syncthreads();

        // ---- scale + causal mask + per-thread row max ----
        const int kvbase = t * 64 + tx * 4;
#pragma unroll
        for (int i = 0; i < 4; i++) {
            int r = ty * 4 + i;
            int qp = qpos0 + r;
            float pm = -3.0e38f;
#pragma unroll
            for (int j = 0; j < 4; j++) {
                float sv = Ss[r * SS_STRIDE + tx*4 + j] * scl;
                int kvp = kvbase + j;
                if (kvp > qp || kvp >= kvlen) sv = -3.0e38f;
                Ss[r * SS_STRIDE + tx*4 + j] = sv;
                pm = fmaxf(pm, sv);
            }
            pmax[r * 16 + tx] = pm;
        }
        __syncthreads();

        // ---- online-softmax row state ----
        if (tid < 64) {
            float m0 = mrow[tid];
            float tm = -3.0e38f;
#pragma unroll
            for (int u = 0; u < 16; u++) tm = fmaxf(tm, pmax[tid*16 + u]);
            float mn = fmaxf(m0, tm);
            float sc = __expf(m0 - mn);
            srow[tid] = sc;
            mrow[tid] = mn;
            lrow[tid] *= sc;
        }
        __syncthreads();

        // ---- exp pass: P -> (Phi, Plo) bf16 + partial sums ----
#pragma unroll
        for (int i = 0; i < 4; i++) {
            int r = ty*4 + i;
            float mr = mrow[r];
            float s = 0.f;
            BF4 PH, PL;
#pragma unroll
            for (int j = 0; j < 4; j++) {
                float pv = __expf(Ss[r * SS_STRIDE + tx*4 + j] - mr);
                s += pv;
                PH.b[j] = __float2bfloat16(pv);
                PL.b[j] = __float2bfloat16(pv - __bfloat162float(PH.b[j]));
            }
            uint32_t poff = (uint32_t)(r * PROWB + tx * 8);
            *(uint2*)(smem + AT_PH + poff) = PH.u;
            *(uint2*)(smem + AT_PL + poff) = PL.u;
            psum[r * 16 + tx] = s;
        }
        __syncthreads();

        if (tid < 64) {
            float s = 0.f;
#pragma unroll
            for (int u = 0; u < 16; u++) s += psum[tid*16 + u];
            lrow[tid] += s;
        }

        // ---- rescale O frags by srow, then O += P@V via HMMA ----
        {
            float s0 = srow[fr0], s1 = srow[fr0 + 8];
#pragma unroll
            for (int j = 0; j < 8; j++) {
                o_acc[j][0] *= s0; o_acc[j][1] *= s0;
                o_acc[j][2] *= s1; o_acc[j][3] *= s1;
            }
            // k over kv (4 chunks of 16); V frags via ldmatrix.trans
#pragma unroll
            for (int kc = 0; kc < 4; kc++) {
                uint32_t aph[4], apl[4];
                ldsm_x4(aph, sb + AT_PH + prow_b + kc * 32 + q_kh);
                ldsm_x4(apl, sb + AT_PL + prow_b + kc * 32 + q_kh);
                uint32_t vrow_off = (uint32_t)((kc * 16 + (lane & 15)) * ATROWB);
#pragma unroll
                for (int j = 0; j < 8; j++) {
                    uint32_t coloff = (uint32_t)((wn * 64 + j * 8) * 2);
                    uint32_t bh[2], bl[2];
                    ldsm_x2t(bh, sb + AT_VH + vrow_off + coloff);
                    ldsm_x2t(bl, sb + AT_VL + vrow_off + coloff);
                    mma16816(o_acc[j], aph, bh);
                    mma16816(o_acc[j], aph, bl);
                    mma16816(o_acc[j], apl, bh);
                }
            }
        }
    }
    __syncthreads();

    // ---- normalize + write O frags to g_o [tok][head][hd] ----
    {
        float inv0 = 1.f / lrow[fr0];
        float inv1 = 1.f / lrow[fr0 + 8];
        size_t r0 = (size_t)(tok0 + fr0);
        size_t r1 = r0 + 8;
#pragma unroll
        for (int j = 0; j < 8; j++) {
            int col = h * HD + wn * 64 + j * 8 + (lane & 3) * 2;
            *(float2*)(g_o + r0 * HIDDEN_D + col) = make_float2(o_acc[j][0] * inv0, o_acc[j][1] * inv0);
            *(float2*)(g_o + r1 * HIDDEN_D + col) = make_float2(o_acc[j][2] * inv1, o_acc[j][3] * inv1);
        }
    }
}

// =====================================================================
// Launch
// =====================================================================
extern "C" void kernel_launch(void* const* d_in, const int* in_sizes, int n_in,
                              void* d_out, int out_size)
{
    const float* hidden = (const float*)d_in[0];
    const float* Wq     = (const float*)d_in[1];
    const float* Wk     = (const float*)d_in[2];
    const float* Wv     = (const float*)d_in[3];
    const float* Wo     = (const float*)d_in[4];
    const float* kc     = (const float*)d_in[5];
    const float* vc     = (const float*)d_in[6];
    const int*   btab   = (const int*)d_in[7];
    const int*   pos    = (const int*)d_in[8];
    const int*   kvl    = (const int*)d_in[9];
    float* out = (float*)d_out;

    float *pq = nullptr, *pk = nullptr, *pv = nullptr, *po = nullptr;
    __nv_bfloat16 *pas = nullptr, *pbs = nullptr;
    cudaGetSymbolAddress((void**)&pq, g_q);
    cudaGetSymbolAddress((void**)&pk, g_k);
    cudaGetSymbolAddress((void**)&pv, g_v);
    cudaGetSymbolAddress((void**)&po, g_o);
    cudaGetSymbolAddress((void**)&pas, g_as);
    cudaGetSymbolAddress((void**)&pbs, g_bs3);

    cudaFuncSetAttribute(mma_gemm_k, cudaFuncAttributeMaxDynamicSharedMemorySize, MG_SMEM);
    cudaFuncSetAttribute(attn_k, cudaFuncAttributeMaxDynamicSharedMemorySize, AT_SMEM);

    const dim3 gsplit_a(TOKENS * 1024 / 256), bsplit(256);
    const dim3 gsplit_w(HIDDEN_D / 32, HIDDEN_D / 32), bsplit_w(32, 8);
    const dim3 gqkv(NQKV / BN, HIDDEN_D / BM), bgemm(512);
    const dim3 gout(HIDDEN_D / BN, HIDDEN_D / BM);

    // A' from hidden; B' rows for Wq|Wk|Wv
    split_a_k<<<gsplit_a, bsplit>>>(hidden, pas);
    split_wt_k<<<gsplit_w, bsplit_w>>>(Wq, pbs);
    split_wt_k<<<gsplit_w, bsplit_w>>>(Wk, pbs + (size_t)4096 * KSPLIT);
    split_wt_k<<<gsplit_w, bsplit_w>>>(Wv, pbs + (size_t)8192 * KSPLIT);

    // fused QKV GEMM (N = 12288)
    mma_gemm_k<<<gqkv, bgemm, MG_SMEM>>>(pas, pbs, pq, pk, pv);

    rope_k<<<(TOKENS * NHEAD * 64) / 256, 256>>>(pos);

    attn_k<<<dim3(QLEN / 64, NHEAD, BATCH), 256, AT_SMEM>>>(kc, vc, btab, pos, kvl);

    // output projection
    split_a_k<<<gsplit_a, bsplit>>>(po, pas);
    split_wt_k<<<gsplit_w, bsplit_w>>>(Wo, pbs);
    mma_gemm_k<<<gout, bgemm, MG_SMEM>>>(pas, pbs, out, out, out);
}

// round 12
// speedup vs baseline: 2.4267x; 1.0339x over previous
#include <cuda_runtime.h>
#include <cuda_bf16.h>
#include <cstdint>
#include <math.h>

// ---------------- problem constants ----------------
#define TOKENS   4096      // B * Q_LEN
#define HIDDEN_D 4096
#define NHEAD    32
#define HD       128
#define QLEN     512
#define BATCH    8
#define BS64     64
#define NBLK     16
#define KVLEN    1024

#define KSPLIT   12288     // 3 * 4096 (hi*hi | hi*lo | lo*hi)
#define NQKV     12288     // fused QKV output columns

// ---------------- scratch (device globals: no runtime alloc allowed) ----------------
__device__ float g_q[(size_t)TOKENS * HIDDEN_D];
__device__ float g_k[(size_t)TOKENS * HIDDEN_D];
__device__ float g_v[(size_t)TOKENS * HIDDEN_D];
__device__ float g_o[(size_t)TOKENS * HIDDEN_D];
__device__ __nv_bfloat16 g_as[(size_t)TOKENS * KSPLIT];     // A' = [hi | hi | lo]
__device__ __nv_bfloat16 g_bs3[(size_t)NQKV * KSPLIT];      // B' rows for Wq|Wk|Wv (or Wo)
// prepped KV planes: 0=K_hi 1=K_lo 2=V_hi 3=V_lo, each [B][KVLEN][NHEAD][HD]
#define PLSTR ((size_t)BATCH * KVLEN * NHEAD * HD)
__device__ __nv_bfloat16 g_kvs[4 * PLSTR];

// =====================================================================
// PTX helpers (baseline ISA only: ldmatrix / mma.sync / cp.async)
// =====================================================================
__device__ __forceinline__ uint32_t smem_u32(const void* p) {
    uint32_t a;
    asm("{ .reg .u64 t; cvta.to.shared.u64 t, %1; cvt.u32.u64 %0, t; }" : "=r"(a) : "l"(p));
    return a;
}
__device__ __forceinline__ void cpasync16(uint32_t s, const void* g) {
    asm volatile("cp.async.cg.shared.global [%0], [%1], 16;" :: "r"(s), "l"(g));
}
#define CP_COMMIT() asm volatile("cp.async.commit_group;" ::: "memory")
#define CP_WAIT(n)  asm volatile("cp.async.wait_group %0;" :: "n"(n) : "memory")

__device__ __forceinline__ void ldsm_x4(uint32_t* r, uint32_t addr) {
    asm volatile("ldmatrix.sync.aligned.m8n8.x4.shared.b16 {%0,%1,%2,%3}, [%4];"
        : "=r"(r[0]), "=r"(r[1]), "=r"(r[2]), "=r"(r[3]) : "r"(addr));
}
__device__ __forceinline__ void ldsm_x2(uint32_t* r, uint32_t addr) {
    asm volatile("ldmatrix.sync.aligned.m8n8.x2.shared.b16 {%0,%1}, [%2];"
        : "=r"(r[0]), "=r"(r[1]) : "r"(addr));
}
__device__ __forceinline__ void ldsm_x2t(uint32_t* r, uint32_t addr) {
    asm volatile("ldmatrix.sync.aligned.m8n8.x2.trans.shared.b16 {%0,%1}, [%2];"
        : "=r"(r[0]), "=r"(r[1]) : "r"(addr));
}
__device__ __forceinline__ void mma16816(float* c, const uint32_t* a, const uint32_t* b) {
    asm volatile("mma.sync.aligned.m16n8k16.row.col.f32.bf16.bf16.f32 "
        "{%0,%1,%2,%3}, {%4,%5,%6,%7}, {%8,%9}, {%0,%1,%2,%3};"
        : "+f"(c[0]), "+f"(c[1]), "+f"(c[2]), "+f"(c[3])
        : "r"(a[0]), "r"(a[1]), "r"(a[2]), "r"(a[3]), "r"(b[0]), "r"(b[1]));
}

union BF4 { __nv_bfloat16 b[4]; uint2 u; };
__device__ __forceinline__ void split4(float4 x, uint2& h, uint2& l) {
    float xs[4] = {x.x, x.y, x.z, x.w};
    BF4 H, L;
#pragma unroll
    for (int i = 0; i < 4; i++) {
        H.b[i] = __float2bfloat16(xs[i]);
        L.b[i] = __float2bfloat16(xs[i] - __bfloat162float(H.b[i]));
    }
    h = H.u; l = L.u;
}

// =====================================================================
// Split kernels: fp32 -> (hi, lo) bf16, arranged for K' = 3*4096 GEMM.
// =====================================================================
__global__ void split_a_k(const float* __restrict__ X, __nv_bfloat16* __restrict__ As)
{
    int idx = blockIdx.x * blockDim.x + threadIdx.x;   // < 4096*1024
    int m = idx >> 10, k4 = idx & 1023;
    float4 x = ((const float4*)X)[(size_t)m * 1024 + k4];
    uint2 h, l;
    split4(x, h, l);
    size_t base = (size_t)m * KSPLIT + k4 * 4;
    *(uint2*)(As + base)        = h;
    *(uint2*)(As + base + 4096) = h;
    *(uint2*)(As + base + 8192) = l;
}

__global__ void split_wt_k(const float* __restrict__ W, __nv_bfloat16* __restrict__ Bs)
{
    __shared__ float t[32][33];
    int n0 = blockIdx.x * 32, k0 = blockIdx.y * 32;
    int tx = threadIdx.x, ty = threadIdx.y;   // (32, 8)
#pragma unroll
    for (int i = 0; i < 4; i++)
        t[ty + i * 8][tx] = W[(size_t)(k0 + ty + i * 8) * HIDDEN_D + n0 + tx];
    __syncthreads();
#pragma unroll
    for (int i = 0; i < 4; i++) {
        int n = n0 + ty + i * 8, kk = k0 + tx;
        float x = t[tx][ty + i * 8];
        __nv_bfloat16 h = __float2bfloat16(x);
        __nv_bfloat16 l = __float2bfloat16(x - __bfloat162float(h));
        size_t base = (size_t)n * KSPLIT + kk;
        Bs[base]        = h;
        Bs[base + 4096] = l;
        Bs[base + 8192] = h;
    }
}

// =====================================================================
// HMMA GEMM with serpentine CTA swizzle (16 grid-rows per group).
// CTA tile 128x256x64, 512 threads, 4-stage cp.async pipeline.
// =====================================================================
#define BM 128
#define BN 256
#define BK 64
#define ROWB 144
#define A_STAGE (BM * ROWB)
#define B_STAGE (BN * ROWB)
#define STAGE_B (A_STAGE + B_STAGE)
#define NSTAGE 4
#define MG_SMEM (STAGE_B * NSTAGE)    // 221184
#define NT_CHUNKS (KSPLIT / BK)       // 192
#define GRSW 16

__global__ __launch_bounds__(512, 1)
void mma_gemm_k(const __nv_bfloat16* __restrict__ A, const __nv_bfloat16* __restrict__ Bt,
                float* __restrict__ C0, float* __restrict__ C1, float* __restrict__ C2)
{
    extern __shared__ char smem[];
    const uint32_t sbase = smem_u32(smem);
    const int tid  = threadIdx.x;
    const int lane = tid & 31, wid = tid >> 5;
    const int warp_m = wid >> 3;
    const int warp_n = wid & 7;

    // serpentine rasterization: 16 rows per group, columns advance slowest
    const int ncol = gridDim.x;
    const int bid = blockIdx.y * ncol + blockIdx.x;
    const int per = GRSW * ncol;
    const int grp = bid / per;
    const int rem = bid - grp * per;
    const int brow = (grp * GRSW + (rem & (GRSW - 1))) * BM;
    const int bcol = (rem / GRSW) * BN;

    float acc[4][4][4];
#pragma unroll
    for (int i = 0; i < 4; i++)
#pragma unroll
        for (int j = 0; j < 4; j++)
#pragma unroll
            for (int q = 0; q < 4; q++) acc[i][j][q] = 0.f;

#define LOAD_STAGE(st, kc) do {                                                        \
    uint32_t sA = sbase + (st) * STAGE_B;                                              \
    uint32_t sB = sA + A_STAGE;                                                        \
    _Pragma("unroll")                                                                  \
    for (int u = 0; u < 2; u++) {                                                      \
        int e = tid + u * 512, r = e >> 3, c = e & 7;                                  \
        cpasync16(sA + r * ROWB + c * 16, A + (size_t)(brow + r) * KSPLIT + (kc) + c * 8); \
    }                                                                                  \
    _Pragma("unroll")                                                                  \
    for (int u = 0; u < 4; u++) {                                                      \
        int e = tid + u * 512, r = e >> 3, c = e & 7;                                  \
        cpasync16(sB + r * ROWB + c * 16, Bt + (size_t)(bcol + r) * KSPLIT + (kc) + c * 8); \
    }                                                                                  \
} while (0)

    LOAD_STAGE(0, 0);      CP_COMMIT();
    LOAD_STAGE(1, BK);     CP_COMMIT();
    LOAD_STAGE(2, 2 * BK); CP_COMMIT();

    const uint32_t a_row = (uint32_t)(warp_m * 64 + (lane & 15));
    const uint32_t a_kh  = (uint32_t)(((lane >> 4) << 3) * 2);
    const uint32_t b_row = (uint32_t)(warp_n * 32 + (lane & 7));
    const uint32_t b_kh  = (uint32_t)((((lane >> 3) & 1) << 3) * 2);

    for (int t = 0; t < NT_CHUNKS; t++) {
        CP_WAIT(2);
        __syncthreads();
        if (t + 3 < NT_CHUNKS) LOAD_STAGE((t + 3) % NSTAGE, (t + 3) * BK);
        CP_COMMIT();

        const uint32_t sA = sbase + (t % NSTAGE) * STAGE_B;
        const uint32_t sB = sA + A_STAGE;

#pragma unroll
        for (int ks = 0; ks < 4; ks++) {
            uint32_t af[4][4], bfr[4][2];
            const uint32_t kb = (uint32_t)(ks * 32);
#pragma unroll
            for (int i = 0; i < 4; i++)
                ldsm_x4(af[i], sA + (a_row + i * 16) * ROWB + kb + a_kh);
#pragma unroll
            for (int j = 0; j < 4; j++)
                ldsm_x2(bfr[j], sB + (b_row + j * 8) * ROWB + kb + b_kh);
#pragma unroll
            for (int i = 0; i < 4; i++)
#pragma unroll
                for (int j = 0; j < 4; j++)
                    mma16816(acc[i][j], af[i], bfr[j]);
        }
    }
#undef LOAD_STAGE

    const int sub = bcol >> 12;
    float* C = (sub == 0) ? C0 : ((sub == 1) ? C1 : C2);
    const int bcolL = bcol & 4095;
#pragma unroll
    for (int i = 0; i < 4; i++) {
        int row0 = brow + warp_m * 64 + i * 16 + (lane >> 2);
#pragma unroll
        for (int j = 0; j < 4; j++) {
            int col = bcolL + warp_n * 32 + j * 8 + (lane & 3) * 2;
            *(float2*)(C + (size_t)row0 * HIDDEN_D + col)       = make_float2(acc[i][j][0], acc[i][j][1]);
            *(float2*)(C + (size_t)(row0 + 8) * HIDDEN_D + col) = make_float2(acc[i][j][2], acc[i][j][3]);
        }
    }
}

// =====================================================================
// RoPE (in-place on g_q, g_k).
// =====================================================================
__global__ void rope_k(const int* __restrict__ pos)
{
    int idx = blockIdx.x * blockDim.x + threadIdx.x;
    if (idx >= TOKENS * NHEAD * 64) return;
    int d   = idx & 63;
    int th  = idx >> 6;
    int tok = th >> 5;
    float p = (float)pos[tok];
    float f = p * exp2f(-0.207620505930454f * (float)d);  // log2(10000)/64
    float s, c;
    sincosf(f, &s, &c);
    size_t base = (size_t)th * HD;
    float x1 = g_q[base + d], x2 = g_q[base + d + 64];
    g_q[base + d]      = x1 * c - x2 * s;
    g_q[base + d + 64] = x2 * c + x1 * s;
    x1 = g_k[base + d]; x2 = g_k[base + d + 64];
    g_k[base + d]      = x1 * c - x2 * s;
    g_k[base + d + 64] = x2 * c + x1 * s;
}

// =====================================================================
// prep_kv: gather K/V (history from paged cache via block table, fresh
// from g_k/g_v post-RoPE), split into hi/lo bf16 planes in g_kvs.
// =====================================================================
__global__ void prep_kv_k(const float* __restrict__ kc, const float* __restrict__ vc,
                          const int* __restrict__ btab)
{
    int idx = blockIdx.x * blockDim.x + threadIdx.x;   // B*1024*32*32
    int c4 = idx & 31;
    int h  = (idx >> 5) & 31;
    int p  = (idx >> 10) & 1023;
    int b  = idx >> 20;
    const float *kp, *vp;
    if (p < 512) {
        int pb = btab[b * NBLK + (p >> 6)];
        size_t s = (((size_t)pb * BS64 + (p & 63)) * NHEAD + h) * HD + c4 * 4;
        kp = kc + s; vp = vc + s;
    } else {
        size_t s = ((size_t)(b * QLEN + (p - 512)) * NHEAD + h) * HD + c4 * 4;
        kp = g_k + s; vp = g_v + s;
    }
    float4 kv = *(const float4*)kp;
    float4 vv = *(const float4*)vp;
    uint2 kh, kl, vh, vl;
    split4(kv, kh, kl);
    split4(vv, vh, vl);
    size_t dst = (((size_t)b * KVLEN + p) * NHEAD + h) * HD + c4 * 4;
    *(uint2*)(g_kvs + dst)             = kh;
    *(uint2*)(g_kvs + PLSTR + dst)     = kl;
    *(uint2*)(g_kvs + 2 * PLSTR + dst) = vh;
    *(uint2*)(g_kvs + 3 * PLSTR + dst) = vl;
}

// =====================================================================
// Flash attention: QK^T and P@V via HMMA (3-term bf16 splits),
// KV tiles cp.async'd from prepped bf16 planes, double-buffered.
// =====================================================================
#define ATROWB 272          // 128 bf16 = 256B + 16B pad
#define PROWB  144
#define SS_STRIDE 65
#define KVPLANE 17408       // 64 rows * 272B
#define KVBUF   (4 * KVPLANE)   // KH KL VH VL

#define AT_QH   0
#define AT_QL   17408
#define AT_KV0  34816
#define AT_KV1  (AT_KV0 + KVBUF)        // 104448
#define AT_SS   (AT_KV1 + KVBUF)        // 174080
#define AT_PH   (AT_SS + 16640)         // 190720
#define AT_PL   (AT_PH + 9216)          // 199936
#define AT_PMAX (AT_PL + 9216)          // 209152
#define AT_PSUM (AT_PMAX + 4096)        // 213248
#define AT_M    (AT_PSUM + 4096)        // 217344
#define AT_L    (AT_M + 256)
#define AT_SC   (AT_L + 256)
#define AT_SMEM (AT_SC + 256)           // 218112

__global__ __launch_bounds__(256, 1)
void attn_k(const int* __restrict__ pos, const int* __restrict__ kvlen_arr)
{
    extern __shared__ char smem[];
    const uint32_t sb = smem_u32(smem);
    float* Ss   = (float*)(smem + AT_SS);
    float* pmax = (float*)(smem + AT_PMAX);
    float* psum = (float*)(smem + AT_PSUM);
    float* mrow = (float*)(smem + AT_M);
    float* lrow = (float*)(smem + AT_L);
    float* srow = (float*)(smem + AT_SC);

    const int qt = blockIdx.x, h = blockIdx.y, b = blockIdx.z;
    const int tid = threadIdx.x;
    const int tx = tid & 15, ty = tid >> 4;
    const int lane = tid & 31, wid = tid >> 5;
    const int wm = wid & 3, wn = wid >> 2;
    const int kvlen = kvlen_arr[b];
    const int tok0  = b * QLEN + qt * 64;
    const int qpos0 = pos[tok0];

    int tmax = (qpos0 + 63) >> 6;
    int tkv  = (kvlen - 1) >> 6;
    if (tmax > tkv) tmax = tkv;
    if (tmax > NBLK - 1) tmax = NBLK - 1;

    // KV tile loader: plane-major cp.async from g_kvs
#define LOAD_KV(bufoff, tt) do {                                                        \
    size_t tbase = ((size_t)b * KVLEN + (tt) * 64) * (NHEAD * HD) + (size_t)h * HD;     \
    _Pragma("unroll")                                                                   \
    for (int u = 0; u < 16; u++) {                                                      \
        int e = tid + u * 256;                                                          \
        int pl = e >> 10, i = e & 1023;                                                 \
        int r = i >> 4, c = i & 15;                                                     \
        cpasync16(sb + (bufoff) + pl * KVPLANE + r * ATROWB + c * 16,                   \
                  g_kvs + (size_t)pl * PLSTR + tbase + (size_t)r * (NHEAD*HD) + c * 8); \
    }                                                                                   \
} while (0)

    // prologue: tile 0 -> buf0
    LOAD_KV(AT_KV0, 0);
    CP_COMMIT();

    // ---- load Q tile, split hi/lo bf16 ----
    const float4* gq4 = (const float4*)g_q;
    for (int i = tid; i < 2048; i += 256) {
        int r = i >> 5, c4 = i & 31;
        float4 qv = gq4[((size_t)(tok0 + r) * NHEAD + h) * (HD/4) + c4];
        uint2 hh, ll;
        split4(qv, hh, ll);
        uint32_t off = (uint32_t)(r * ATROWB + c4 * 8);
        *(uint2*)(smem + AT_QH + off) = hh;
        *(uint2*)(smem + AT_QL + off) = ll;
    }
    if (tid < 64) { mrow[tid] = -3.0e38f; lrow[tid] = 0.f; }

    float o_acc[8][4];
#pragma unroll
    for (int j = 0; j < 8; j++)
#pragma unroll
        for (int q = 0; q < 4; q++) o_acc[j][q] = 0.f;

    const float scl = 0.0883883476483184f;   // 1/sqrt(128)

    const uint32_t qrow_b = (uint32_t)((wm * 16 + (lane & 15)) * ATROWB);
    const uint32_t q_kh   = (uint32_t)(((lane >> 4) << 3) * 2);
    const uint32_t k_kh   = (uint32_t)((((lane >> 3) & 1) << 3) * 2);
    const uint32_t prow_b = (uint32_t)((wm * 16 + (lane & 15)) * PROWB);
    const int fr0 = wm * 16 + (lane >> 2);

    for (int t = 0; t <= tmax; t++) {
        __syncthreads();   // all warps done with buf[(t+1)&1] (iter t-1) and Ss/P
        const uint32_t bufc = (t & 1) ? AT_KV1 : AT_KV0;
        const uint32_t bufn = (t & 1) ? AT_KV0 : AT_KV1;
        if (t + 1 <= tmax) {
            LOAD_KV(bufn, t + 1);
            CP_COMMIT();
            CP_WAIT(1);    // current tile's group done
        } else {
            CP_WAIT(0);
        }
        __syncthreads();

        const uint32_t kh_b = sb + bufc;
        const uint32_t kl_b = kh_b + KVPLANE;
        const uint32_t vh_b = kh_b + 2 * KVPLANE;
        const uint32_t vl_b = kh_b + 3 * KVPLANE;

        // ---- S = Q K^T via HMMA: qh*kh + qh*kl + ql*kh ----
        {
            float sc4[4][4];
#pragma unroll
            for (int j = 0; j < 4; j++)
#pragma unroll
                for (int q = 0; q < 4; q++) sc4[j][q] = 0.f;

            const uint32_t qb_t[3] = { sb + AT_QH, sb + AT_QH, sb + AT_QL };
            const uint32_t kb_t[3] = { kh_b, kl_b, kh_b };
#pragma unroll
            for (int tm = 0; tm < 3; tm++) {
                const uint32_t qb = qb_t[tm], kb = kb_t[tm];
#pragma unroll
                for (int kc = 0; kc < 8; kc++) {
                    uint32_t af[4];
                    ldsm_x4(af, qb + qrow_b + kc * 32 + q_kh);
#pragma unroll
                    for (int j = 0; j < 4; j++) {
                        uint32_t bf2[2];
                        ldsm_x2(bf2, kb + (uint32_t)((wn * 32 + j * 8 + (lane & 7)) * ATROWB) + kc * 32 + k_kh);
                        mma16816(sc4[j], af, bf2);
                    }
                }
            }
            const int c0 = wn * 32 + (lane & 3) * 2;
#pragma unroll
            for (int j = 0; j < 4; j++) {
                Ss[fr0 * SS_STRIDE + c0 + j * 8]           = sc4[j][0];
                Ss[fr0 * SS_STRIDE + c0 + j * 8 + 1]       = sc4[j][1];
                Ss[(fr0 + 8) * SS_STRIDE + c0 + j * 8]     = sc4[j][2];
                Ss[(fr0 + 8) * SS_STRIDE + c0 + j * 8 + 1] = sc4[j][3];
            }
        }
        __syncthreads();

        // ---- scale + causal mask + per-thread row max ----
        const int kvbase = t * 64 + tx * 4;
#pragma unroll
        for (int i = 0; i < 4; i++) {
            int r = ty * 4 + i;
            int qp = qpos0 + r;
            float pm = -3.0e38f;
#pragma unroll
            for (int j = 0; j < 4; j++) {
                float sv = Ss[r * SS_STRIDE + tx*4 + j] * scl;
                int kvp = kvbase + j;
                if (kvp > qp || kvp >= kvlen) sv = -3.0e38f;
                Ss[r * SS_STRIDE + tx*4 + j] = sv;
                pm = fmaxf(pm, sv);
            }
            pmax[r * 16 + tx] = pm;
        }
        __syncthreads();

        // ---- online-softmax row state ----
        if (tid < 64) {
            float m0 = mrow[tid];
            float tm = -3.0e38f;
#pragma unroll
            for (int u = 0; u < 16; u++) tm = fmaxf(tm, pmax[tid*16 + u]);
            float mn = fmaxf(m0, tm);
            float sc = __expf(m0 - mn);
            srow[tid] = sc;
            mrow[tid] = mn;
            lrow[tid] *= sc;
        }
        __syncthreads();

        // ---- exp pass: P -> (Phi, Plo) bf16 + partial sums ----
#pragma unroll
        for (int i = 0; i < 4; i++) {
            int r = ty*4 + i;
            float mr = mrow[r];
            float s = 0.f;
            BF4 PH, PL;
#pragma unroll
            for (int j = 0; j < 4; j++) {
                float pv = __expf(Ss[r * SS_STRIDE + tx*4 + j] - mr);
                s += pv;
                PH.b[j] = __float2bfloat16(pv);
                PL.b[j] = __float2bfloat16(pv - __bfloat162float(PH.b[j]));
            }
            uint32_t poff = (uint32_t)(r * PROWB + tx * 8);
            *(uint2*)(smem + AT_PH + poff) = PH.u;
            *(uint2*)(smem + AT_PL + poff) = PL.u;
            psum[r * 16 + tx] = s;
        }
        __syncthreads();

        if (tid < 64) {
            float s = 0.f;
#pragma unroll
            for (int u = 0; u < 16; u++) s += psum[tid*16 + u];
            lrow[tid] += s;
        }

        // ---- rescale O frags, then O += P@V via HMMA ----
        {
            float s0 = srow[fr0], s1 = srow[fr0 + 8];
#pragma unroll
            for (int j = 0; j < 8; j++) {
                o_acc[j][0] *= s0; o_acc[j][1] *= s0;
                o_acc[j][2] *= s1; o_acc[j][3] *= s1;
            }
#pragma unroll
            for (int kc = 0; kc < 4; kc++) {
                uint32_t aph[4], apl[4];
                ldsm_x4(aph, sb + AT_PH + prow_b + kc * 32 + q_kh);
                ldsm_x4(apl, sb + AT_PL + prow_b + kc * 32 + q_kh);
                uint32_t vrow_off = (uint32_t)((kc * 16 + (lane & 15)) * ATROWB);
#pragma unroll
                for (int j = 0; j < 8; j++) {
                    uint32_t coloff = (uint32_t)((wn * 64 + j * 8) * 2);
                    uint32_t bh[2], bl[2];
                    ldsm_x2t(bh, vh_b + vrow_off + coloff);
                    ldsm_x2t(bl, vl_b + vrow_off + coloff);
                    mma16816(o_acc[j], aph, bh);
                    mma16816(o_acc[j], aph, bl);
                    mma16816(o_acc[j], apl, bh);
                }
            }
        }
    }
#undef LOAD_KV
    __syncthreads();

    // ---- normalize + write O frags to g_o [tok][head][hd] ----
    {
        float inv0 = 1.f / lrow[fr0];
        float inv1 = 1.f / lrow[fr0 + 8];
        size_t r0 = (size_t)(tok0 + fr0);
        size_t r1 = r0 + 8;
#pragma unroll
        for (int j = 0; j < 8; j++) {
            int col = h * HD + wn * 64 + j * 8 + (lane & 3) * 2;
            *(float2*)(g_o + r0 * HIDDEN_D + col) = make_float2(o_acc[j][0] * inv0, o_acc[j][1] * inv0);
            *(float2*)(g_o + r1 * HIDDEN_D + col) = make_float2(o_acc[j][2] * inv1, o_acc[j][3] * inv1);
        }
    }
}

// =====================================================================
// Launch
// =====================================================================
extern "C" void kernel_launch(void* const* d_in, const int* in_sizes, int n_in,
                              void* d_out, int out_size)
{
    const float* hidden = (const float*)d_in[0];
    const float* Wq     = (const float*)d_in[1];
    const float* Wk     = (const float*)d_in[2];
    const float* Wv     = (const float*)d_in[3];
    const float* Wo     = (const float*)d_in[4];
    const float* kc     = (const float*)d_in[5];
    const float* vc     = (const float*)d_in[6];
    const int*   btab   = (const int*)d_in[7];
    const int*   pos    = (const int*)d_in[8];
    const int*   kvl    = (const int*)d_in[9];
    float* out = (float*)d_out;

    float *pq = nullptr, *pk = nullptr, *pv = nullptr, *po = nullptr;
    __nv_bfloat16 *pas = nullptr, *pbs = nullptr;
    cudaGetSymbolAddress((void**)&pq, g_q);
    cudaGetSymbolAddress((void**)&pk, g_k);
    cudaGetSymbolAddress((void**)&pv, g_v);
    cudaGetSymbolAddress((void**)&po, g_o);
    cudaGetSymbolAddress((void**)&pas, g_as);
    cudaGetSymbolAddress((void**)&pbs, g_bs3);

    cudaFuncSetAttribute(mma_gemm_k, cudaFuncAttributeMaxDynamicSharedMemorySize, MG_SMEM);
    cudaFuncSetAttribute(attn_k, cudaFuncAttributeMaxDynamicSharedMemorySize, AT_SMEM);

    const dim3 gsplit_a(TOKENS * 1024 / 256), bsplit(256);
    const dim3 gsplit_w(HIDDEN_D / 32, HIDDEN_D / 32), bsplit_w(32, 8);
    const dim3 gqkv(NQKV / BN, HIDDEN_D / BM), bgemm(512);
    const dim3 gout(HIDDEN_D / BN, HIDDEN_D / BM);

    // A' from hidden; B' rows for Wq|Wk|Wv
    split_a_k<<<gsplit_a, bsplit>>>(hidden, pas);
    split_wt_k<<<gsplit_w, bsplit_w>>>(Wq, pbs);
    split_wt_k<<<gsplit_w, bsplit_w>>>(Wk, pbs + (size_t)4096 * KSPLIT);
    split_wt_k<<<gsplit_w, bsplit_w>>>(Wv, pbs + (size_t)8192 * KSPLIT);

    // fused QKV GEMM (N = 12288)
    mma_gemm_k<<<gqkv, bgemm, MG_SMEM>>>(pas, pbs, pq, pk, pv);

    rope_k<<<(TOKENS * NHEAD * 64) / 256, 256>>>(pos);

    // gather + split KV planes (history from cache, fresh post-RoPE)
    prep_kv_k<<<(BATCH * KVLEN * NHEAD * 32) / 256, 256>>>(kc, vc, btab);

    attn_k<<<dim3(QLEN / 64, NHEAD, BATCH), 256, AT_SMEM>>>(pos, kvl);

    // output projection
    split_a_k<<<gsplit_a, bsplit>>>(po, pas);
    split_wt_k<<<gsplit_w, bsplit_w>>>(Wo, pbs);
    mma_gemm_k<<<gout, bgemm, MG_SMEM>>>(pas, pbs, out, out, out);
}

// round 13
// speedup vs baseline: 3.2356x; 1.3333x over previous
#include <cuda_runtime.h>
#include <cuda_bf16.h>
#include <cuda_fp16.h>
#include <cstdint>
#include <math.h>

// ---------------- problem constants ----------------
#define TOKENS   4096      // B * Q_LEN
#define HIDDEN_D 4096
#define NHEAD    32
#define HD       128
#define QLEN     512
#define BATCH    8
#define BS64     64
#define NBLK     16
#define KVLEN    1024

#define KA       8192      // A' = [hi | lo] fp16
#define KB       4096      // B' = [hi] fp16 (wrapped)
#define NQKV     12288     // fused QKV output columns

// ---------------- scratch (device globals: no runtime alloc allowed) ----------------
__device__ float g_q[(size_t)TOKENS * HIDDEN_D];
__device__ float g_k[(size_t)TOKENS * HIDDEN_D];
__device__ float g_v[(size_t)TOKENS * HIDDEN_D];
__device__ float g_o[(size_t)TOKENS * HIDDEN_D];
__device__ __half g_as[(size_t)TOKENS * KA];        // A' = [hi | lo]
__device__ __half g_bs3[(size_t)NQKV * KB];         // B' rows for Wq|Wk|Wv (or Wo)
// prepped KV planes: 0=K_hi 1=K_lo 2=V_hi 3=V_lo (bf16), each [B][KVLEN][NHEAD][HD]
#define PLSTR ((size_t)BATCH * KVLEN * NHEAD * HD)
__device__ __nv_bfloat16 g_kvs[4 * PLSTR];

// =====================================================================
// PTX helpers
// =====================================================================
__device__ __forceinline__ uint32_t smem_u32(const void* p) {
    uint32_t a;
    asm("{ .reg .u64 t; cvta.to.shared.u64 t, %1; cvt.u32.u64 %0, t; }" : "=r"(a) : "l"(p));
    return a;
}
__device__ __forceinline__ void cpasync16(uint32_t s, const void* g) {
    asm volatile("cp.async.cg.shared.global [%0], [%1], 16;" :: "r"(s), "l"(g));
}
#define CP_COMMIT() asm volatile("cp.async.commit_group;" ::: "memory")
#define CP_WAIT(n)  asm volatile("cp.async.wait_group %0;" :: "n"(n) : "memory")

__device__ __forceinline__ void ldsm_x4(uint32_t* r, uint32_t addr) {
    asm volatile("ldmatrix.sync.aligned.m8n8.x4.shared.b16 {%0,%1,%2,%3}, [%4];"
        : "=r"(r[0]), "=r"(r[1]), "=r"(r[2]), "=r"(r[3]) : "r"(addr));
}
__device__ __forceinline__ void ldsm_x2(uint32_t* r, uint32_t addr) {
    asm volatile("ldmatrix.sync.aligned.m8n8.x2.shared.b16 {%0,%1}, [%2];"
        : "=r"(r[0]), "=r"(r[1]) : "r"(addr));
}
__device__ __forceinline__ void ldsm_x2t(uint32_t* r, uint32_t addr) {
    asm volatile("ldmatrix.sync.aligned.m8n8.x2.trans.shared.b16 {%0,%1}, [%2];"
        : "=r"(r[0]), "=r"(r[1]) : "r"(addr));
}
// bf16 mma (attention)
__device__ __forceinline__ void mma16816(float* c, const uint32_t* a, const uint32_t* b) {
    asm volatile("mma.sync.aligned.m16n8k16.row.col.f32.bf16.bf16.f32 "
        "{%0,%1,%2,%3}, {%4,%5,%6,%7}, {%8,%9}, {%0,%1,%2,%3};"
        : "+f"(c[0]), "+f"(c[1]), "+f"(c[2]), "+f"(c[3])
        : "r"(a[0]), "r"(a[1]), "r"(a[2]), "r"(a[3]), "r"(b[0]), "r"(b[1]));
}
// fp16 mma (dense GEMMs)
__device__ __forceinline__ void mma16816h(float* c, const uint32_t* a, const uint32_t* b) {
    asm volatile("mma.sync.aligned.m16n8k16.row.col.f32.f16.f16.f32 "
        "{%0,%1,%2,%3}, {%4,%5,%6,%7}, {%8,%9}, {%0,%1,%2,%3};"
        : "+f"(c[0]), "+f"(c[1]), "+f"(c[2]), "+f"(c[3])
        : "r"(a[0]), "r"(a[1]), "r"(a[2]), "r"(a[3]), "r"(b[0]), "r"(b[1]));
}

union BF4 { __nv_bfloat16 b[4]; uint2 u; };
__device__ __forceinline__ void split4(float4 x, uint2& h, uint2& l) {
    float xs[4] = {x.x, x.y, x.z, x.w};
    BF4 H, L;
#pragma unroll
    for (int i = 0; i < 4; i++) {
        H.b[i] = __float2bfloat16(xs[i]);
        L.b[i] = __float2bfloat16(xs[i] - __bfloat162float(H.b[i]));
    }
    h = H.u; l = L.u;
}
union HF4 { __half b[4]; uint2 u; };
__device__ __forceinline__ void split4h(float4 x, uint2& h, uint2& l) {
    float xs[4] = {x.x, x.y, x.z, x.w};
    HF4 H, L;
#pragma unroll
    for (int i = 0; i < 4; i++) {
        H.b[i] = __float2half_rn(xs[i]);
        L.b[i] = __float2half_rn(xs[i] - __half2float(H.b[i]));
    }
    h = H.u; l = L.u;
}

// =====================================================================
// Split kernels (fp16 2-term): A' = [hi | lo], B' = [hi] (transposed W)
// =====================================================================
__global__ void split_a_k(const float* __restrict__ X, __half* __restrict__ As)
{
    int idx = blockIdx.x * blockDim.x + threadIdx.x;   // < 4096*1024
    int m = idx >> 10, k4 = idx & 1023;
    float4 x = ((const float4*)X)[(size_t)m * 1024 + k4];
    uint2 h, l;
    split4h(x, h, l);
    size_t base = (size_t)m * KA + k4 * 4;
    *(uint2*)(As + base)        = h;
    *(uint2*)(As + base + 4096) = l;
}

__global__ void split_wt_k(const float* __restrict__ W, __half* __restrict__ Bs)
{
    __shared__ float t[32][33];
    int n0 = blockIdx.x * 32, k0 = blockIdx.y * 32;
    int tx = threadIdx.x, ty = threadIdx.y;   // (32, 8)
#pragma unroll
    for (int i = 0; i < 4; i++)
        t[ty + i * 8][tx] = W[(size_t)(k0 + ty + i * 8) * HIDDEN_D + n0 + tx];
    __syncthreads();
#pragma unroll
    for (int i = 0; i < 4; i++) {
        int n = n0 + ty + i * 8, kk = k0 + tx;
        Bs[(size_t)n * KB + kk] = __float2half_rn(t[tx][ty + i * 8]);
    }
}

// =====================================================================
// fp16 HMMA GEMM: C[4096, N] = A'[4096,8192] x B'[N,4096]^T (B k-wrapped)
// CTA tile 128x256x64, 512 threads, 4-stage cp.async, serpentine swizzle.
// =====================================================================
#define BM 128
#define BN 256
#define BK 64
#define ROWB 144
#define A_STAGE (BM * ROWB)
#define B_STAGE (BN * ROWB)
#define STAGE_B (A_STAGE + B_STAGE)
#define NSTAGE 4
#define MG_SMEM (STAGE_B * NSTAGE)    // 221184
#define NT_CHUNKS (KA / BK)           // 128
#define GRSW 16

__global__ __launch_bounds__(512, 1)
void mma_gemm_k(const __half* __restrict__ A, const __half* __restrict__ Bt,
                float* __restrict__ C0, float* __restrict__ C1, float* __restrict__ C2)
{
    extern __shared__ char smem[];
    const uint32_t sbase = smem_u32(smem);
    const int tid  = threadIdx.x;
    const int lane = tid & 31, wid = tid >> 5;
    const int warp_m = wid >> 3;
    const int warp_n = wid & 7;

    const int ncol = gridDim.x;
    const int bid = blockIdx.y * ncol + blockIdx.x;
    const int per = GRSW * ncol;
    const int grp = bid / per;
    const int rem = bid - grp * per;
    const int brow = (grp * GRSW + (rem & (GRSW - 1))) * BM;
    const int bcol = (rem / GRSW) * BN;

    float acc[4][4][4];
#pragma unroll
    for (int i = 0; i < 4; i++)
#pragma unroll
        for (int j = 0; j < 4; j++)
#pragma unroll
            for (int q = 0; q < 4; q++) acc[i][j][q] = 0.f;

#define LOAD_STAGE(st, kc) do {                                                        \
    uint32_t sA = sbase + (st) * STAGE_B;                                              \
    uint32_t sB = sA + A_STAGE;                                                        \
    const int kbw = (kc) & (KB - 1);                                                   \
    _Pragma("unroll")                                                                  \
    for (int u = 0; u < 2; u++) {                                                      \
        int e = tid + u * 512, r = e >> 3, c = e & 7;                                  \
        cpasync16(sA + r * ROWB + c * 16, A + (size_t)(brow + r) * KA + (kc) + c * 8); \
    }                                                                                  \
    _Pragma("unroll")                                                                  \
    for (int u = 0; u < 4; u++) {                                                      \
        int e = tid + u * 512, r = e >> 3, c = e & 7;                                  \
        cpasync16(sB + r * ROWB + c * 16, Bt + (size_t)(bcol + r) * KB + kbw + c * 8); \
    }                                                                                  \
} while (0)

    LOAD_STAGE(0, 0);      CP_COMMIT();
    LOAD_STAGE(1, BK);     CP_COMMIT();
    LOAD_STAGE(2, 2 * BK); CP_COMMIT();

    const uint32_t a_row = (uint32_t)(warp_m * 64 + (lane & 15));
    const uint32_t a_kh  = (uint32_t)(((lane >> 4) << 3) * 2);
    const uint32_t b_row = (uint32_t)(warp_n * 32 + (lane & 7));
    const uint32_t b_kh  = (uint32_t)((((lane >> 3) & 1) << 3) * 2);

    for (int t = 0; t < NT_CHUNKS; t++) {
        CP_WAIT(2);
        __syncthreads();
        if (t + 3 < NT_CHUNKS) LOAD_STAGE((t + 3) % NSTAGE, (t + 3) * BK);
        CP_COMMIT();

        const uint32_t sA = sbase + (t % NSTAGE) * STAGE_B;
        const uint32_t sB = sA + A_STAGE;

#pragma unroll
        for (int ks = 0; ks < 4; ks++) {
            uint32_t af[4][4], bfr[4][2];
            const uint32_t kb = (uint32_t)(ks * 32);
#pragma unroll
            for (int i = 0; i < 4; i++)
                ldsm_x4(af[i], sA + (a_row + i * 16) * ROWB + kb + a_kh);
#pragma unroll
            for (int j = 0; j < 4; j++)
                ldsm_x2(bfr[j], sB + (b_row + j * 8) * ROWB + kb + b_kh);
#pragma unroll
            for (int i = 0; i < 4; i++)
#pragma unroll
                for (int j = 0; j < 4; j++)
                    mma16816h(acc[i][j], af[i], bfr[j]);
        }
    }
#undef LOAD_STAGE

    const int sub = bcol >> 12;
    float* C = (sub == 0) ? C0 : ((sub == 1) ? C1 : C2);
    const int bcolL = bcol & 4095;
#pragma unroll
    for (int i = 0; i < 4; i++) {
        int row0 = brow + warp_m * 64 + i * 16 + (lane >> 2);
#pragma unroll
        for (int j = 0; j < 4; j++) {
            int col = bcolL + warp_n * 32 + j * 8 + (lane & 3) * 2;
            *(float2*)(C + (size_t)row0 * HIDDEN_D + col)       = make_float2(acc[i][j][0], acc[i][j][1]);
            *(float2*)(C + (size_t)(row0 + 8) * HIDDEN_D + col) = make_float2(acc[i][j][2], acc[i][j][3]);
        }
    }
}

// =====================================================================
// RoPE (in-place on g_q, g_k).
// =====================================================================
__global__ void rope_k(const int* __restrict__ pos)
{
    int idx = blockIdx.x * blockDim.x + threadIdx.x;
    if (idx >= TOKENS * NHEAD * 64) return;
    int d   = idx & 63;
    int th  = idx >> 6;
    int tok = th >> 5;
    float p = (float)pos[tok];
    float f = p * exp2f(-0.207620505930454f * (float)d);  // log2(10000)/64
    float s, c;
    sincosf(f, &s, &c);
    size_t base = (size_t)th * HD;
    float x1 = g_q[base + d], x2 = g_q[base + d + 64];
    g_q[base + d]      = x1 * c - x2 * s;
    g_q[base + d + 64] = x2 * c + x1 * s;
    x1 = g_k[base + d]; x2 = g_k[base + d + 64];
    g_k[base + d]      = x1 * c - x2 * s;
    g_k[base + d + 64] = x2 * c + x1 * s;
}

// =====================================================================
// prep_kv: gather K/V, split into hi/lo bf16 planes in g_kvs.
// =====================================================================
__global__ void prep_kv_k(const float* __restrict__ kc, const float* __restrict__ vc,
                          const int* __restrict__ btab)
{
    int idx = blockIdx.x * blockDim.x + threadIdx.x;   // B*1024*32*32
    int c4 = idx & 31;
    int h  = (idx >> 5) & 31;
    int p  = (idx >> 10) & 1023;
    int b  = idx >> 20;
    const float *kp, *vp;
    if (p < 512) {
        int pb = btab[b * NBLK + (p >> 6)];
        size_t s = (((size_t)pb * BS64 + (p & 63)) * NHEAD + h) * HD + c4 * 4;
        kp = kc + s; vp = vc + s;
    } else {
        size_t s = ((size_t)(b * QLEN + (p - 512)) * NHEAD + h) * HD + c4 * 4;
        kp = g_k + s; vp = g_v + s;
    }
    float4 kv = *(const float4*)kp;
    float4 vv = *(const float4*)vp;
    uint2 kh, kl, vh, vl;
    split4(kv, kh, kl);
    split4(vv, vh, vl);
    size_t dst = (((size_t)b * KVLEN + p) * NHEAD + h) * HD + c4 * 4;
    *(uint2*)(g_kvs + dst)             = kh;
    *(uint2*)(g_kvs + PLSTR + dst)     = kl;
    *(uint2*)(g_kvs + 2 * PLSTR + dst) = vh;
    *(uint2*)(g_kvs + 3 * PLSTR + dst) = vl;
}

// =====================================================================
// Flash attention (unchanged bf16 3-term HMMA path, double-buffered KV).
// =====================================================================
#define ATROWB 272
#define PROWB  144
#define SS_STRIDE 65
#define KVPLANE 17408
#define KVBUF   (4 * KVPLANE)

#define AT_QH   0
#define AT_QL   17408
#define AT_KV0  34816
#define AT_KV1  (AT_KV0 + KVBUF)
#define AT_SS   (AT_KV1 + KVBUF)
#define AT_PH   (AT_SS + 16640)
#define AT_PL   (AT_PH + 9216)
#define AT_PMAX (AT_PL + 9216)
#define AT_PSUM (AT_PMAX + 4096)
#define AT_M    (AT_PSUM + 4096)
#define AT_L    (AT_M + 256)
#define AT_SC   (AT_L + 256)
#define AT_SMEM (AT_SC + 256)           // 218112

__global__ __launch_bounds__(256, 1)
void attn_k(const int* __restrict__ pos, const int* __restrict__ kvlen_arr)
{
    extern __shared__ char smem[];
    const uint32_t sb = smem_u32(smem);
    float* Ss   = (float*)(smem + AT_SS);
    float* pmax = (float*)(smem + AT_PMAX);
    float* psum = (float*)(smem + AT_PSUM);
    float* mrow = (float*)(smem + AT_M);
    float* lrow = (float*)(smem + AT_L);
    float* srow = (float*)(smem + AT_SC);

    const int qt = blockIdx.x, h = blockIdx.y, b = blockIdx.z;
    const int tid = threadIdx.x;
    const int tx = tid & 15, ty = tid >> 4;
    const int lane = tid & 31, wid = tid >> 5;
    const int wm = wid & 3, wn = wid >> 2;
    const int kvlen = kvlen_arr[b];
    const int tok0  = b * QLEN + qt * 64;
    const int qpos0 = pos[tok0];

    int tmax = (qpos0 + 63) >> 6;
    int tkv  = (kvlen - 1) >> 6;
    if (tmax > tkv) tmax = tkv;
    if (tmax > NBLK - 1) tmax = NBLK - 1;

#define LOAD_KV(bufoff, tt) do {                                                        \
    size_t tbase = ((size_t)b * KVLEN + (tt) * 64) * (NHEAD * HD) + (size_t)h * HD;     \
    _Pragma("unroll")                                                                   \
    for (int u = 0; u < 16; u++) {                                                      \
        int e = tid + u * 256;                                                          \
        int pl = e >> 10, i = e & 1023;                                                 \
        int r = i >> 4, c = i & 15;                                                     \
        cpasync16(sb + (bufoff) + pl * KVPLANE + r * ATROWB + c * 16,                   \
                  g_kvs + (size_t)pl * PLSTR + tbase + (size_t)r * (NHEAD*HD) + c * 8); \
    }                                                                                   \
} while (0)

    LOAD_KV(AT_KV0, 0);
    CP_COMMIT();

    const float4* gq4 = (const float4*)g_q;
    for (int i = tid; i < 2048; i += 256) {
        int r = i >> 5, c4 = i & 31;
        float4 qv = gq4[((size_t)(tok0 + r) * NHEAD + h) * (HD/4) + c4];
        uint2 hh, ll;
        split4(qv, hh, ll);
        uint32_t off = (uint32_t)(r * ATROWB + c4 * 8);
        *(uint2*)(smem + AT_QH + off) = hh;
        *(uint2*)(smem + AT_QL + off) = ll;
    }
    if (tid < 64) { mrow[tid] = -3.0e38f; lrow[tid] = 0.f; }

    float o_acc[8][4];
#pragma unroll
    for (int j = 0; j < 8; j++)
#pragma unroll
        for (int q = 0; q < 4; q++) o_acc[j][q] = 0.f;

    const float scl = 0.0883883476483184f;

    const uint32_t qrow_b = (uint32_t)((wm * 16 + (lane & 15)) * ATROWB);
    const uint32_t q_kh   = (uint32_t)(((lane >> 4) << 3) * 2);
    const uint32_t k_kh   = (uint32_t)((((lane >> 3) & 1) << 3) * 2);
    const uint32_t prow_b = (uint32_t)((wm * 16 + (lane & 15)) * PROWB);
    const int fr0 = wm * 16 + (lane >> 2);

    for (int t = 0; t <= tmax; t++) {
        __syncthreads();
        const uint32_t bufc = (t & 1) ? AT_KV1 : AT_KV0;
        const uint32_t bufn = (t & 1) ? AT_KV0 : AT_KV1;
        if (t + 1 <= tmax) {
            LOAD_KV(bufn, t + 1);
            CP_COMMIT();
            CP_WAIT(1);
        } else {
            CP_WAIT(0);
        }
        __syncthreads();

        const uint32_t kh_b = sb + bufc;
        const uint32_t kl_b = kh_b + KVPLANE;
        const uint32_t vh_b = kh_b + 2 * KVPLANE;
        const uint32_t vl_b = kh_b + 3 * KVPLANE;

        // ---- S = Q K^T via HMMA: qh*kh + qh*kl + ql*kh ----
        {
            float sc4[4][4];
#pragma unroll
            for (int j = 0; j < 4; j++)
#pragma unroll
                for (int q = 0; q < 4; q++) sc4[j][q] = 0.f;

            const uint32_t qb_t[3] = { sb + AT_QH, sb + AT_QH, sb + AT_QL };
            const uint32_t kb_t[3] = { kh_b, kl_b, kh_b };
#pragma unroll
            for (int tm = 0; tm < 3; tm++) {
                const uint32_t qb = qb_t[tm], kb = kb_t[tm];
#pragma unroll
                for (int kc = 0; kc < 8; kc++) {
                    uint32_t af[4];
                    ldsm_x4(af, qb + qrow_b + kc * 32 + q_kh);
#pragma unroll
                    for (int j = 0; j < 4; j++) {
                        uint32_t bf2[2];
                        ldsm_x2(bf2, kb + (uint32_t)((wn * 32 + j * 8 + (lane & 7)) * ATROWB) + kc * 32 + k_kh);
                        mma16816(sc4[j], af, bf2);
                    }
                }
            }
            const int c0 = wn * 32 + (lane & 3) * 2;
#pragma unroll
            for (int j = 0; j < 4; j++) {
                Ss[fr0 * SS_STRIDE + c0 + j * 8]           = sc4[j][0];
                Ss[fr0 * SS_STRIDE + c0 + j * 8 + 1]       = sc4[j][1];
                Ss[(fr0 + 8) * SS_STRIDE + c0 + j * 8]     = sc4[j][2];
                Ss[(fr0 + 8) * SS_STRIDE + c0 + j * 8 + 1] = sc4[j][3];
            }
        }
        __syncthreads();

        // ---- scale + causal mask + per-thread row max ----
        const int kvbase = t * 64 + tx * 4;
#pragma unroll
        for (int i = 0; i < 4; i++) {
            int r = ty * 4 + i;
            int qp = qpos0 + r;
            float pm = -3.0e38f;
#pragma unroll
            for (int j = 0; j < 4; j++) {
                float sv = Ss[r * SS_STRIDE + tx*4 + j] * scl;
                int kvp = kvbase + j;
                if (kvp > qp || kvp >= kvlen) sv = -3.0e38f;
                Ss[r * SS_STRIDE + tx*4 + j] = sv;
                pm = fmaxf(pm, sv);
            }
            pmax[r * 16 + tx] = pm;
        }
        __syncthreads();

        if (tid < 64) {
            float m0 = mrow[tid];
            float tm = -3.0e38f;
#pragma unroll
            for (int u = 0; u < 16; u++) tm = fmaxf(tm, pmax[tid*16 + u]);
            float mn = fmaxf(m0, tm);
            float sc = __expf(m0 - mn);
            srow[tid] = sc;
            mrow[tid] = mn;
            lrow[tid] *= sc;
        }
        __syncthreads();

#pragma unroll
        for (int i = 0; i < 4; i++) {
            int r = ty*4 + i;
            float mr = mrow[r];
            float s = 0.f;
            BF4 PH, PL;
#pragma unroll
            for (int j = 0; j < 4; j++) {
                float pv = __expf(Ss[r * SS_STRIDE + tx*4 + j] - mr);
                s += pv;
                PH.b[j] = __float2bfloat16(pv);
                PL.b[j] = __float2bfloat16(pv - __bfloat162float(PH.b[j]));
            }
            uint32_t poff = (uint32_t)(r * PROWB + tx * 8);
            *(uint2*)(smem + AT_PH + poff) = PH.u;
            *(uint2*)(smem + AT_PL + poff) = PL.u;
            psum[r * 16 + tx] = s;
        }
        __syncthreads();

        if (tid < 64) {
            float s = 0.f;
#pragma unroll
            for (int u = 0; u < 16; u++) s += psum[tid*16 + u];
            lrow[tid] += s;
        }

        {
            float s0 = srow[fr0], s1 = srow[fr0 + 8];
#pragma unroll
            for (int j = 0; j < 8; j++) {
                o_acc[j][0] *= s0; o_acc[j][1] *= s0;
                o_acc[j][2] *= s1; o_acc[j][3] *= s1;
            }
#pragma unroll
            for (int kc = 0; kc < 4; kc++) {
                uint32_t aph[4], apl[4];
                ldsm_x4(aph, sb + AT_PH + prow_b + kc * 32 + q_kh);
                ldsm_x4(apl, sb + AT_PL + prow_b + kc * 32 + q_kh);
                uint32_t vrow_off = (uint32_t)((kc * 16 + (lane & 15)) * ATROWB);
#pragma unroll
                for (int j = 0; j < 8; j++) {
                    uint32_t coloff = (uint32_t)((wn * 64 + j * 8) * 2);
                    uint32_t bh[2], bl[2];
                    ldsm_x2t(bh, vh_b + vrow_off + coloff);
                    ldsm_x2t(bl, vl_b + vrow_off + coloff);
                    mma16816(o_acc[j], aph, bh);
                    mma16816(o_acc[j], aph, bl);
                    mma16816(o_acc[j], apl, bh);
                }
            }
        }
    }
#undef LOAD_KV
    __syncthreads();

    {
        float inv0 = 1.f / lrow[fr0];
        float inv1 = 1.f / lrow[fr0 + 8];
        size_t r0 = (size_t)(tok0 + fr0);
        size_t r1 = r0 + 8;
#pragma unroll
        for (int j = 0; j < 8; j++) {
            int col = h * HD + wn * 64 + j * 8 + (lane & 3) * 2;
            *(float2*)(g_o + r0 * HIDDEN_D + col) = make_float2(o_acc[j][0] * inv0, o_acc[j][1] * inv0);
            *(float2*)(g_o + r1 * HIDDEN_D + col) = make_float2(o_acc[j][2] * inv1, o_acc[j][3] * inv1);
        }
    }
}

// =====================================================================
// Launch
// =====================================================================
extern "C" void kernel_launch(void* const* d_in, const int* in_sizes, int n_in,
                              void* d_out, int out_size)
{
    const float* hidden = (const float*)d_in[0];
    const float* Wq     = (const float*)d_in[1];
    const float* Wk     = (const float*)d_in[2];
    const float* Wv     = (const float*)d_in[3];
    const float* Wo     = (const float*)d_in[4];
    const float* kc     = (const float*)d_in[5];
    const float* vc     = (const float*)d_in[6];
    const int*   btab   = (const int*)d_in[7];
    const int*   pos    = (const int*)d_in[8];
    const int*   kvl    = (const int*)d_in[9];
    float* out = (float*)d_out;

    float *pq = nullptr, *pk = nullptr, *pv = nullptr, *po = nullptr;
    __half *pas = nullptr, *pbs = nullptr;
    cudaGetSymbolAddress((void**)&pq, g_q);
    cudaGetSymbolAddress((void**)&pk, g_k);
    cudaGetSymbolAddress((void**)&pv, g_v);
    cudaGetSymbolAddress((void**)&po, g_o);
    cudaGetSymbolAddress((void**)&pas, g_as);
    cudaGetSymbolAddress((void**)&pbs, g_bs3);

    cudaFuncSetAttribute(mma_gemm_k, cudaFuncAttributeMaxDynamicSharedMemorySize, MG_SMEM);
    cudaFuncSetAttribute(attn_k, cudaFuncAttributeMaxDynamicSharedMemorySize, AT_SMEM);

    const dim3 gsplit_a(TOKENS * 1024 / 256), bsplit(256);
    const dim3 gsplit_w(HIDDEN_D / 32, HIDDEN_D / 32), bsplit_w(32, 8);
    const dim3 gqkv(NQKV / BN, HIDDEN_D / BM), bgemm(512);
    const dim3 gout(HIDDEN_D / BN, HIDDEN_D / BM);

    // A' from hidden; B' rows for Wq|Wk|Wv (fp16 hi only, row stride 4096)
    split_a_k<<<gsplit_a, bsplit>>>(hidden, pas);
    split_wt_k<<<gsplit_w, bsplit_w>>>(Wq, pbs);
    split_wt_k<<<gsplit_w, bsplit_w>>>(Wk, pbs + (size_t)4096 * KB);
    split_wt_k<<<gsplit_w, bsplit_w>>>(Wv, pbs + (size_t)8192 * KB);

    // fused QKV GEMM (N = 12288)
    mma_gemm_k<<<gqkv, bgemm, MG_SMEM>>>(pas, pbs, pq, pk, pv);

    rope_k<<<(TOKENS * NHEAD * 64) / 256, 256>>>(pos);

    prep_kv_k<<<(BATCH * KVLEN * NHEAD * 32) / 256, 256>>>(kc, vc, btab);

    attn_k<<<dim3(QLEN / 64, NHEAD, BATCH), 256, AT_SMEM>>>(pos, kvl);

    // output projection
    split_a_k<<<gsplit_a, bsplit>>>(po, pas);
    split_wt_k<<<gsplit_w, bsplit_w>>>(Wo, pbs);
    mma_gemm_k<<<gout, bgemm, MG_SMEM>>>(pas, pbs, out, out, out);
}

// round 15
// speedup vs baseline: 3.4081x; 1.0533x over previous
#include <cuda_runtime.h>
#include <cuda_bf16.h>
#include <cuda_fp16.h>
#include <cstdint>
#include <math.h>

// ---------------- problem constants ----------------
#define TOKENS   4096      // B * Q_LEN
#define HIDDEN_D 4096
#define NHEAD    32
#define HD       128
#define QLEN     512
#define BATCH    8
#define BS64     64
#define NBLK     16
#define KVLEN    1024

#define KA       8192      // A' = [hi | lo] fp16
#define KB       4096      // B' = [hi] fp16 (wrapped)
#define NQKV     12288     // fused QKV output columns

// ---------------- scratch (device globals: no runtime alloc allowed) ----------------
__device__ float g_q[(size_t)TOKENS * HIDDEN_D];
__device__ float g_k[(size_t)TOKENS * HIDDEN_D];
__device__ float g_v[(size_t)TOKENS * HIDDEN_D];
__device__ float g_o[(size_t)TOKENS * HIDDEN_D];
__device__ __half g_as[(size_t)TOKENS * KA];        // A' = [hi | lo]
__device__ __half g_bs3[(size_t)NQKV * KB];         // B' rows for Wq|Wk|Wv (or Wo)
// prepped KV planes: 0=K_hi 1=K_lo 2=V_hi 3=V_lo (bf16), each [B][KVLEN][NHEAD][HD]
#define PLSTR ((size_t)BATCH * KVLEN * NHEAD * HD)
__device__ __nv_bfloat16 g_kvs[4 * PLSTR];

// =====================================================================
// PTX helpers
// =====================================================================
__device__ __forceinline__ uint32_t smem_u32(const void* p) {
    uint32_t a;
    asm("{ .reg .u64 t; cvta.to.shared.u64 t, %1; cvt.u32.u64 %0, t; }" : "=r"(a) : "l"(p));
    return a;
}
__device__ __forceinline__ void cpasync16(uint32_t s, const void* g) {
    asm volatile("cp.async.cg.shared.global [%0], [%1], 16;" :: "r"(s), "l"(g));
}
#define CP_COMMIT() asm volatile("cp.async.commit_group;" ::: "memory")
#define CP_WAIT(n)  asm volatile("cp.async.wait_group %0;" :: "n"(n) : "memory")

__device__ __forceinline__ void ldsm_x4(uint32_t* r, uint32_t addr) {
    asm volatile("ldmatrix.sync.aligned.m8n8.x4.shared.b16 {%0,%1,%2,%3}, [%4];"
        : "=r"(r[0]), "=r"(r[1]), "=r"(r[2]), "=r"(r[3]) : "r"(addr));
}
__device__ __forceinline__ void ldsm_x2(uint32_t* r, uint32_t addr) {
    asm volatile("ldmatrix.sync.aligned.m8n8.x2.shared.b16 {%0,%1}, [%2];"
        : "=r"(r[0]), "=r"(r[1]) : "r"(addr));
}
__device__ __forceinline__ void ldsm_x2t(uint32_t* r, uint32_t addr) {
    asm volatile("ldmatrix.sync.aligned.m8n8.x2.trans.shared.b16 {%0,%1}, [%2];"
        : "=r"(r[0]), "=r"(r[1]) : "r"(addr));
}
// bf16 mma (attention)
__device__ __forceinline__ void mma16816(float* c, const uint32_t* a, const uint32_t* b) {
    asm volatile("mma.sync.aligned.m16n8k16.row.col.f32.bf16.bf16.f32 "
        "{%0,%1,%2,%3}, {%4,%5,%6,%7}, {%8,%9}, {%0,%1,%2,%3};"
        : "+f"(c[0]), "+f"(c[1]), "+f"(c[2]), "+f"(c[3])
        : "r"(a[0]), "r"(a[1]), "r"(a[2]), "r"(a[3]), "r"(b[0]), "r"(b[1]));
}
// fp16 mma (dense GEMMs)
__device__ __forceinline__ void mma16816h(float* c, const uint32_t* a, const uint32_t* b) {
    asm volatile("mma.sync.aligned.m16n8k16.row.col.f32.f16.f16.f32 "
        "{%0,%1,%2,%3}, {%4,%5,%6,%7}, {%8,%9}, {%0,%1,%2,%3};"
        : "+f"(c[0]), "+f"(c[1]), "+f"(c[2]), "+f"(c[3])
        : "r"(a[0]), "r"(a[1]), "r"(a[2]), "r"(a[3]), "r"(b[0]), "r"(b[1]));
}

union BF4 { __nv_bfloat16 b[4]; uint2 u; };
__device__ __forceinline__ void split4(float4 x, uint2& h, uint2& l) {
    float xs[4] = {x.x, x.y, x.z, x.w};
    BF4 H, L;
#pragma unroll
    for (int i = 0; i < 4; i++) {
        H.b[i] = __float2bfloat16(xs[i]);
        L.b[i] = __float2bfloat16(xs[i] - __bfloat162float(H.b[i]));
    }
    h = H.u; l = L.u;
}
union HF4 { __half b[4]; uint2 u; };
__device__ __forceinline__ void split4h(float4 x, uint2& h, uint2& l) {
    float xs[4] = {x.x, x.y, x.z, x.w};
    HF4 H, L;
#pragma unroll
    for (int i = 0; i < 4; i++) {
        H.b[i] = __float2half_rn(xs[i]);
        L.b[i] = __float2half_rn(xs[i] - __half2float(H.b[i]));
    }
    h = H.u; l = L.u;
}

// =====================================================================
// Split kernels (fp16 2-term): A' = [hi | lo], B' = [hi] (transposed W)
// =====================================================================
__global__ void split_a_k(const float* __restrict__ X, __half* __restrict__ As)
{
    int idx = blockIdx.x * blockDim.x + threadIdx.x;   // < 4096*1024
    int m = idx >> 10, k4 = idx & 1023;
    float4 x = ((const float4*)X)[(size_t)m * 1024 + k4];
    uint2 h, l;
    split4h(x, h, l);
    size_t base = (size_t)m * KA + k4 * 4;
    *(uint2*)(As + base)        = h;
    *(uint2*)(As + base + 4096) = l;
}

__global__ void split_wt_k(const float* __restrict__ W, __half* __restrict__ Bs)
{
    __shared__ float t[32][33];
    int n0 = blockIdx.x * 32, k0 = blockIdx.y * 32;
    int tx = threadIdx.x, ty = threadIdx.y;   // (32, 8)
#pragma unroll
    for (int i = 0; i < 4; i++)
        t[ty + i * 8][tx] = W[(size_t)(k0 + ty + i * 8) * HIDDEN_D + n0 + tx];
    __syncthreads();
#pragma unroll
    for (int i = 0; i < 4; i++) {
        int n = n0 + ty + i * 8, kk = k0 + tx;
        Bs[(size_t)n * KB + kk] = __float2half_rn(t[tx][ty + i * 8]);
    }
}

// =====================================================================
// fp16 HMMA GEMM: C[4096, N] = A'[4096,8192] x B'[N,4096]^T (B k-wrapped)
// CTA tile 128x128x64, 256 threads (8 warps, warp tile 64x32),
// 3-stage cp.async pipeline, 2 CTAs/SM for barrier-latency hiding.
// =====================================================================
#define BM 128
#define BN 128
#define BK 64
#define ROWB 144
#define A_STAGE (BM * ROWB)           // 18432
#define B_STAGE (BN * ROWB)           // 18432
#define STAGE_B (A_STAGE + B_STAGE)   // 36864
#define NSTAGE 3
#define MG_SMEM (STAGE_B * NSTAGE)    // 110592
#define NT_CHUNKS (KA / BK)           // 128
#define GRSW 16

__global__ __launch_bounds__(256, 2)
void mma_gemm_k(const __half* __restrict__ A, const __half* __restrict__ Bt,
                float* __restrict__ C0, float* __restrict__ C1, float* __restrict__ C2)
{
    extern __shared__ char smem[];
    const uint32_t sbase = smem_u32(smem);
    const int tid  = threadIdx.x;
    const int lane = tid & 31, wid = tid >> 5;
    const int warp_m = wid >> 2;          // 0..1 (64 rows each)
    const int warp_n = wid & 3;           // 0..3 (32 cols each)

    const int ncol = gridDim.x;
    const int bid = blockIdx.y * ncol + blockIdx.x;
    const int per = GRSW * ncol;
    const int grp = bid / per;
    const int rem = bid - grp * per;
    const int brow = (grp * GRSW + (rem & (GRSW - 1))) * BM;
    const int bcol = (rem / GRSW) * BN;

    float acc[4][4][4];
#pragma unroll
    for (int i = 0; i < 4; i++)
#pragma unroll
        for (int j = 0; j < 4; j++)
#pragma unroll
            for (int q = 0; q < 4; q++) acc[i][j][q] = 0.f;

    // per stage: A tile 128 rows x 8 chunks(16B) = 1024, B same; 4 each per thread
#define LOAD_STAGE(st, kc) do {                                                        \
    uint32_t sA = sbase + (st) * STAGE_B;                                              \
    uint32_t sB = sA + A_STAGE;                                                        \
    const int kbw = (kc) & (KB - 1);                                                   \
    _Pragma("unroll")                                                                  \
    for (int u = 0; u < 4; u++) {                                                      \
        int e = tid + u * 256, r = e >> 3, c = e & 7;                                  \
        cpasync16(sA + r * ROWB + c * 16, A + (size_t)(brow + r) * KA + (kc) + c * 8); \
    }                                                                                  \
    _Pragma("unroll")                                                                  \
    for (int u = 0; u < 4; u++) {                                                      \
        int e = tid + u * 256, r = e >> 3, c = e & 7;                                  \
        cpasync16(sB + r * ROWB + c * 16, Bt + (size_t)(bcol + r) * KB + kbw + c * 8); \
    }                                                                                  \
} while (0)

    LOAD_STAGE(0, 0);  CP_COMMIT();
    LOAD_STAGE(1, BK); CP_COMMIT();

    const uint32_t a_row = (uint32_t)(warp_m * 64 + (lane & 15));
    const uint32_t a_kh  = (uint32_t)(((lane >> 4) << 3) * 2);
    const uint32_t b_row = (uint32_t)(warp_n * 32 + (lane & 7));
    const uint32_t b_kh  = (uint32_t)((((lane >> 3) & 1) << 3) * 2);

    for (int t = 0; t < NT_CHUNKS; t++) {
        CP_WAIT(1);
        __syncthreads();
        if (t + 2 < NT_CHUNKS) LOAD_STAGE((t + 2) % NSTAGE, (t + 2) * BK);
        CP_COMMIT();

        const uint32_t sA = sbase + (t % NSTAGE) * STAGE_B;
        const uint32_t sB = sA + A_STAGE;

#pragma unroll
        for (int ks = 0; ks < 4; ks++) {
            uint32_t af[4][4], bfr[4][2];
            const uint32_t kb = (uint32_t)(ks * 32);
#pragma unroll
            for (int i = 0; i < 4; i++)
                ldsm_x4(af[i], sA + (a_row + i * 16) * ROWB + kb + a_kh);
#pragma unroll
            for (int j = 0; j < 4; j++)
                ldsm_x2(bfr[j], sB + (b_row + j * 8) * ROWB + kb + b_kh);
#pragma unroll
            for (int i = 0; i < 4; i++)
#pragma unroll
                for (int j = 0; j < 4; j++)
                    mma16816h(acc[i][j], af[i], bfr[j]);
        }
        __syncthreads();
    }
#undef LOAD_STAGE

    const int sub = bcol >> 12;
    float* C = (sub == 0) ? C0 : ((sub == 1) ? C1 : C2);
    const int bcolL = bcol & 4095;
#pragma unroll
    for (int i = 0; i < 4; i++) {
        int row0 = brow + warp_m * 64 + i * 16 + (lane >> 2);
#pragma unroll
        for (int j = 0; j < 4; j++) {
            int col = bcolL + warp_n * 32 + j * 8 + (lane & 3) * 2;
            *(float2*)(C + (size_t)row0 * HIDDEN_D + col)       = make_float2(acc[i][j][0], acc[i][j][1]);
            *(float2*)(C + (size_t)(row0 + 8) * HIDDEN_D + col) = make_float2(acc[i][j][2], acc[i][j][3]);
        }
    }
}

// =====================================================================
// RoPE (in-place on g_q, g_k).
// =====================================================================
__global__ void rope_k(const int* __restrict__ pos)
{
    int idx = blockIdx.x * blockDim.x + threadIdx.x;
    if (idx >= TOKENS * NHEAD * 64) return;
    int d   = idx & 63;
    int th  = idx >> 6;
    int tok = th >> 5;
    float p = (float)pos[tok];
    float f = p * exp2f(-0.207620505930454f * (float)d);  // log2(10000)/64
    float s, c;
    sincosf(f, &s, &c);
    size_t base = (size_t)th * HD;
    float x1 = g_q[base + d], x2 = g_q[base + d + 64];
    g_q[base + d]      = x1 * c - x2 * s;
    g_q[base + d + 64] = x2 * c + x1 * s;
    x1 = g_k[base + d]; x2 = g_k[base + d + 64];
    g_k[base + d]      = x1 * c - x2 * s;
    g_k[base + d + 64] = x2 * c + x1 * s;
}

// =====================================================================
// prep_kv: gather K/V, split into hi/lo bf16 planes in g_kvs.
// =====================================================================
__global__ void prep_kv_k(const float* __restrict__ kc, const float* __restrict__ vc,
                          const int* __restrict__ btab)
{
    int idx = blockIdx.x * blockDim.x + threadIdx.x;   // B*1024*32*32
    int c4 = idx & 31;
    int h  = (idx >> 5) & 31;
    int p  = (idx >> 10) & 1023;
    int b  = idx >> 20;
    const float *kp, *vp;
    if (p < 512) {
        int pb = btab[b * NBLK + (p >> 6)];
        size_t s = (((size_t)pb * BS64 + (p & 63)) * NHEAD + h) * HD + c4 * 4;
        kp = kc + s; vp = vc + s;
    } else {
        size_t s = ((size_t)(b * QLEN + (p - 512)) * NHEAD + h) * HD + c4 * 4;
        kp = g_k + s; vp = g_v + s;
    }
    float4 kv = *(const float4*)kp;
    float4 vv = *(const float4*)vp;
    uint2 kh, kl, vh, vl;
    split4(kv, kh, kl);
    split4(vv, vh, vl);
    size_t dst = (((size_t)b * KVLEN + p) * NHEAD + h) * HD + c4 * 4;
    *(uint2*)(g_kvs + dst)             = kh;
    *(uint2*)(g_kvs + PLSTR + dst)     = kl;
    *(uint2*)(g_kvs + 2 * PLSTR + dst) = vh;
    *(uint2*)(g_kvs + 3 * PLSTR + dst) = vl;
}

// =====================================================================
// Flash attention (bf16 3-term HMMA path, double-buffered KV).
// =====================================================================
#define ATROWB 272
#define PROWB  144
#define SS_STRIDE 65
#define KVPLANE 17408
#define KVBUF   (4 * KVPLANE)

#define AT_QH   0
#define AT_QL   17408
#define AT_KV0  34816
#define AT_KV1  (AT_KV0 + KVBUF)
#define AT_SS   (AT_KV1 + KVBUF)
#define AT_PH   (AT_SS + 16640)
#define AT_PL   (AT_PH + 9216)
#define AT_PMAX (AT_PL + 9216)
#define AT_PSUM (AT_PMAX + 4096)
#define AT_M    (AT_PSUM + 4096)
#define AT_L    (AT_M + 256)
#define AT_SC   (AT_L + 256)
#define AT_SMEM (AT_SC + 256)           // 218112

__global__ __launch_bounds__(256, 1)
void attn_k(const int* __restrict__ pos, const int* __restrict__ kvlen_arr)
{
    extern __shared__ char smem[];
    const uint32_t sb = smem_u32(smem);
    float* Ss   = (float*)(smem + AT_SS);
    float* pmax = (float*)(smem + AT_PMAX);
    float* psum = (float*)(smem + AT_PSUM);
    float* mrow = (float*)(smem + AT_M);
    float* lrow = (float*)(smem + AT_L);
    float* srow = (float*)(smem + AT_SC);

    const int qt = blockIdx.x, h = blockIdx.y, b = blockIdx.z;
    const int tid = threadIdx.x;
    const int tx = tid & 15, ty = tid >> 4;
    const int lane = tid & 31, wid = tid >> 5;
    const int wm = wid & 3, wn = wid >> 2;
    const int kvlen = kvlen_arr[b];
    const int tok0  = b * QLEN + qt * 64;
    const int qpos0 = pos[tok0];

    int tmax = (qpos0 + 63) >> 6;
    int tkv  = (kvlen - 1) >> 6;
    if (tmax > tkv) tmax = tkv;
    if (tmax > NBLK - 1) tmax = NBLK - 1;

#define LOAD_KV(bufoff, tt) do {                                                        \
    size_t tbase = ((size_t)b * KVLEN + (tt) * 64) * (NHEAD * HD) + (size_t)h * HD;     \
    _Pragma("unroll")                                                                   \
    for (int u = 0; u < 16; u++) {                                                      \
        int e = tid + u * 256;                                                          \
        int pl = e >> 10, i = e & 1023;                                                 \
        int r = i >> 4, c = i & 15;                                                     \
        cpasync16(sb + (bufoff) + pl * KVPLANE + r * ATROWB + c * 16,                   \
                  g_kvs + (size_t)pl * PLSTR + tbase + (size_t)r * (NHEAD*HD) + c * 8); \
    }                                                                                   \
} while (0)

    LOAD_KV(AT_KV0, 0);
    CP_COMMIT();

    const float4* gq4 = (const float4*)g_q;
    for (int i = tid; i < 2048; i += 256) {
        int r = i >> 5, c4 = i & 31;
        float4 qv = gq4[((size_t)(tok0 + r) * NHEAD + h) * (HD/4) + c4];
        uint2 hh, ll;
        split4(qv, hh, ll);
        uint32_t off = (uint32_t)(r * ATROWB + c4 * 8);
        *(uint2*)(smem + AT_QH + off) = hh;
        *(uint2*)(smem + AT_QL + off) = ll;
    }
    if (tid < 64) { mrow[tid] = -3.0e38f; lrow[tid] = 0.f; }

    float o_acc[8][4];
#pragma unroll
    for (int j = 0; j < 8; j++)
#pragma unroll
        for (int q = 0; q < 4; q++) o_acc[j][q] = 0.f;

    const float scl = 0.0883883476483184f;

    const uint32_t qrow_b = (uint32_t)((wm * 16 + (lane & 15)) * ATROWB);
    const uint32_t q_kh   = (uint32_t)(((lane >> 4) << 3) * 2);
    const uint32_t k_kh   = (uint32_t)((((lane >> 3) & 1) << 3) * 2);
    const uint32_t prow_b = (uint32_t)((wm * 16 + (lane & 15)) * PROWB);
    const int fr0 = wm * 16 + (lane >> 2);

    for (int t = 0; t <= tmax; t++) {
        __syncthreads();
        const uint32_t bufc = (t & 1) ? AT_KV1 : AT_KV0;
        const uint32_t bufn = (t & 1) ? AT_KV0 : AT_KV1;
        if (t + 1 <= tmax) {
            LOAD_KV(bufn, t + 1);
            CP_COMMIT();
            CP_WAIT(1);
        } else {
            CP_WAIT(0);
        }
        __syncthreads();

        const uint32_t kh_b = sb + bufc;
        const uint32_t kl_b = kh_b + KVPLANE;
        const uint32_t vh_b = kh_b + 2 * KVPLANE;
        const uint32_t vl_b = kh_b + 3 * KVPLANE;

        // ---- S = Q K^T via HMMA: qh*kh + qh*kl + ql*kh ----
        {
            float sc4[4][4];
#pragma unroll
            for (int j = 0; j < 4; j++)
#pragma unroll
                for (int q = 0; q < 4; q++) sc4[j][q] = 0.f;

            const uint32_t qb_t[3] = { sb + AT_QH, sb + AT_QH, sb + AT_QL };
            const uint32_t kb_t[3] = { kh_b, kl_b, kh_b };
#pragma unroll
            for (int tm = 0; tm < 3; tm++) {
                const uint32_t qb = qb_t[tm], kb = kb_t[tm];
#pragma unroll
                for (int kc = 0; kc < 8; kc++) {
                    uint32_t af[4];
                    ldsm_x4(af, qb + qrow_b + kc * 32 + q_kh);
#pragma unroll
                    for (int j = 0; j < 4; j++) {
                        uint32_t bf2[2];
                        ldsm_x2(bf2, kb + (uint32_t)((wn * 32 + j * 8 + (lane & 7)) * ATROWB) + kc * 32 + k_kh);
                        mma16816(sc4[j], af, bf2);
                    }
                }
            }
            const int c0 = wn * 32 + (lane & 3) * 2;
#pragma unroll
            for (int j = 0; j < 4; j++) {
                Ss[fr0 * SS_STRIDE + c0 + j * 8]           = sc4[j][0];
                Ss[fr0 * SS_STRIDE + c0 + j * 8 + 1]       = sc4[j][1];
                Ss[(fr0 + 8) * SS_STRIDE + c0 + j * 8]     = sc4[j][2];
                Ss[(fr0 + 8) * SS_STRIDE + c0 + j * 8 + 1] = sc4[j][3];
            }
        }
        __syncthreads();

        // ---- scale + causal mask + per-thread row max ----
        const int kvbase = t * 64 + tx * 4;
#pragma unroll
        for (int i = 0; i < 4; i++) {
            int r = ty * 4 + i;
            int qp = qpos0 + r;
            float pm = -3.0e38f;
#pragma unroll
            for (int j = 0; j < 4; j++) {
                float sv = Ss[r * SS_STRIDE + tx*4 + j] * scl;
                int kvp = kvbase + j;
                if (kvp > qp || kvp >= kvlen) sv = -3.0e38f;
                Ss[r * SS_STRIDE + tx*4 + j] = sv;
                pm = fmaxf(pm, sv);
            }
            pmax[r * 16 + tx] = pm;
        }
        __syncthreads();

        if (tid < 64) {
            float m0 = mrow[tid];
            float tm = -3.0e38f;
#pragma unroll
            for (int u = 0; u < 16; u++) tm = fmaxf(tm, pmax[tid*16 + u]);
            float mn = fmaxf(m0, tm);
            float sc = __expf(m0 - mn);
            srow[tid] = sc;
            mrow[tid] = mn;
            lrow[tid] *= sc;
        }
        __syncthreads();

#pragma unroll
        for (int i = 0; i < 4; i++) {
            int r = ty*4 + i;
            float mr = mrow[r];
            float s = 0.f;
            BF4 PH, PL;
#pragma unroll
            for (int j = 0; j < 4; j++) {
                float pv = __expf(Ss[r * SS_STRIDE + tx*4 + j] - mr);
                s += pv;
                PH.b[j] = __float2bfloat16(pv);
                PL.b[j] = __float2bfloat16(pv - __bfloat162float(PH.b[j]));
            }
            uint32_t poff = (uint32_t)(r * PROWB + tx * 8);
            *(uint2*)(smem + AT_PH + poff) = PH.u;
            *(uint2*)(smem + AT_PL + poff) = PL.u;
            psum[r * 16 + tx] = s;
        }
        __syncthreads();

        if (tid < 64) {
            float s = 0.f;
#pragma unroll
            for (int u = 0; u < 16; u++) s += psum[tid*16 + u];
            lrow[tid] += s;
        }

        {
            float s0 = srow[fr0], s1 = srow[fr0 + 8];
#pragma unroll
            for (int j = 0; j < 8; j++) {
                o_acc[j][0] *= s0; o_acc[j][1] *= s0;
                o_acc[j][2] *= s1; o_acc[j][3] *= s1;
            }
#pragma unroll
            for (int kc = 0; kc < 4; kc++) {
                uint32_t aph[4], apl[4];
                ldsm_x4(aph, sb + AT_PH + prow_b + kc * 32 + q_kh);
                ldsm_x4(apl, sb + AT_PL + prow_b + kc * 32 + q_kh);
                uint32_t vrow_off = (uint32_t)((kc * 16 + (lane & 15)) * ATROWB);
#pragma unroll
                for (int j = 0; j < 8; j++) {
                    uint32_t coloff = (uint32_t)((wn * 64 + j * 8) * 2);
                    uint32_t bh[2], bl[2];
                    ldsm_x2t(bh, vh_b + vrow_off + coloff);
                    ldsm_x2t(bl, vl_b + vrow_off + coloff);
                    mma16816(o_acc[j], aph, bh);
                    mma16816(o_acc[j], aph, bl);
                    mma16816(o_acc[j], apl, bh);
                }
            }
        }
    }
#undef LOAD_KV
    __syncthreads();

    {
        float inv0 = 1.f / lrow[fr0];
        float inv1 = 1.f / lrow[fr0 + 8];
        size_t r0 = (size_t)(tok0 + fr0);
        size_t r1 = r0 + 8;
#pragma unroll
        for (int j = 0; j < 8; j++) {
            int col = h * HD + wn * 64 + j * 8 + (lane & 3) * 2;
            *(float2*)(g_o + r0 * HIDDEN_D + col) = make_float2(o_acc[j][0] * inv0, o_acc[j][1] * inv0);
            *(float2*)(g_o + r1 * HIDDEN_D + col) = make_float2(o_acc[j][2] * inv1, o_acc[j][3] * inv1);
        }
    }
}

// =====================================================================
// Launch
// =====================================================================
extern "C" void kernel_launch(void* const* d_in, const int* in_sizes, int n_in,
                              void* d_out, int out_size)
{
    const float* hidden = (const float*)d_in[0];
    const float* Wq     = (const float*)d_in[1];
    const float* Wk     = (const float*)d_in[2];
    const float* Wv     = (const float*)d_in[3];
    const float* Wo     = (const float*)d_in[4];
    const float* kc     = (const float*)d_in[5];
    const float* vc     = (const float*)d_in[6];
    const int*   btab   = (const int*)d_in[7];
    const int*   pos    = (const int*)d_in[8];
    const int*   kvl    = (const int*)d_in[9];
    float* out = (float*)d_out;

    float *pq = nullptr, *pk = nullptr, *pv = nullptr, *po = nullptr;
    __half *pas = nullptr, *pbs = nullptr;
    cudaGetSymbolAddress((void**)&pq, g_q);
    cudaGetSymbolAddress((void**)&pk, g_k);
    cudaGetSymbolAddress((void**)&pv, g_v);
    cudaGetSymbolAddress((void**)&po, g_o);
    cudaGetSymbolAddress((void**)&pas, g_as);
    cudaGetSymbolAddress((void**)&pbs, g_bs3);

    cudaFuncSetAttribute(mma_gemm_k, cudaFuncAttributeMaxDynamicSharedMemorySize, MG_SMEM);
    cudaFuncSetAttribute(attn_k, cudaFuncAttributeMaxDynamicSharedMemorySize, AT_SMEM);

    const dim3 gsplit_a(TOKENS * 1024 / 256), bsplit(256);
    const dim3 gsplit_w(HIDDEN_D / 32, HIDDEN_D / 32), bsplit_w(32, 8);
    const dim3 gqkv(NQKV / BN, HIDDEN_D / BM), bgemm(256);
    const dim3 gout(HIDDEN_D / BN, HIDDEN_D / BM);

    // A' from hidden; B' rows for Wq|Wk|Wv (fp16 hi only, row stride 4096)
    split_a_k<<<gsplit_a, bsplit>>>(hidden, pas);
    split_wt_k<<<gsplit_w, bsplit_w>>>(Wq, pbs);
    split_wt_k<<<gsplit_w, bsplit_w>>>(Wk, pbs + (size_t)4096 * KB);
    split_wt_k<<<gsplit_w, bsplit_w>>>(Wv, pbs + (size_t)8192 * KB);

    // fused QKV GEMM (N = 12288)
    mma_gemm_k<<<gqkv, bgemm, MG_SMEM>>>(pas, pbs, pq, pk, pv);

    rope_k<<<(TOKENS * NHEAD * 64) / 256, 256>>>(pos);

    prep_kv_k<<<(BATCH * KVLEN * NHEAD * 32) / 256, 256>>>(kc, vc, btab);

    attn_k<<<dim3(QLEN / 64, NHEAD, BATCH), 256, AT_SMEM>>>(pos, kvl);

    // output projection
    split_a_k<<<gsplit_a, bsplit>>>(po, pas);
    split_wt_k<<<gsplit_w, bsplit_w>>>(Wo, pbs);
    mma_gemm_k<<<gout, bgemm, MG_SMEM>>>(pas, pbs, out, out, out);
}